// round 11
// baseline (speedup 1.0000x reference)
#include <cuda_runtime.h>
#include <cuda_bf16.h>
#include <cuda_fp16.h>
#include <cstdint>
#include <math.h>

#define BB 2
#define SS 2048
#define DD 768
#define FF 3072
#define HH 12
#define DKK 64
#define NROW (BB*SS)   // 4096

// ---------------------------------------------------------------- scratch
__device__ __nv_bfloat16 g_thi[NROW*DD];
__device__ __half        g_t16[NROW*DD];
__device__ __nv_bfloat16 g_qb[NROW*DD], g_kb[NROW*DD], g_vb[NROW*DD];
__device__ float g_x2[NROW*DD];
__device__ __nv_bfloat16 g_chi[NROW*DD];
__device__ __half        g_h1[NROW*FF];
__device__ __nv_bfloat16 g_wqhi[DD*DD];
__device__ __nv_bfloat16 g_wkhi[DD*DD];
__device__ __nv_bfloat16 g_wvhi[DD*DD];
__device__ __nv_bfloat16 g_wohi[DD*DD];
__device__ __half        g_w1h[FF*DD];   // [F,D] = w1^T (fp16)
__device__ __half        g_w2h[DD*FF];   // [D,F] = w2^T (fp16)

// ---------------------------------------------------------------- helpers
__device__ __forceinline__ uint32_t smem_to_u32(const void* p) {
    uint32_t a;
    asm("{ .reg .u64 t; cvta.to.shared.u64 t, %1; cvt.u32.u64 %0, t; }" : "=r"(a) : "l"(p));
    return a;
}
__device__ __forceinline__ void ldsm_x4(uint32_t (&r)[4], uint32_t addr) {
    asm volatile("ldmatrix.sync.aligned.m8n8.x4.shared.b16 {%0,%1,%2,%3}, [%4];"
                 : "=r"(r[0]), "=r"(r[1]), "=r"(r[2]), "=r"(r[3]) : "r"(addr));
}
__device__ __forceinline__ void ldsm_x4_t(uint32_t (&r)[4], uint32_t addr) {
    asm volatile("ldmatrix.sync.aligned.m8n8.x4.trans.shared.b16 {%0,%1,%2,%3}, [%4];"
                 : "=r"(r[0]), "=r"(r[1]), "=r"(r[2]), "=r"(r[3]) : "r"(addr));
}
__device__ __forceinline__ void mma_bf16(float (&c)[4], const uint32_t (&a)[4], const uint32_t (&b)[2]) {
    asm volatile("mma.sync.aligned.m16n8k16.row.col.f32.bf16.bf16.f32 "
                 "{%0,%1,%2,%3}, {%4,%5,%6,%7}, {%8,%9}, {%0,%1,%2,%3};"
                 : "+f"(c[0]), "+f"(c[1]), "+f"(c[2]), "+f"(c[3])
                 : "r"(a[0]), "r"(a[1]), "r"(a[2]), "r"(a[3]), "r"(b[0]), "r"(b[1]));
}
__device__ __forceinline__ void mma_f16(float (&c)[4], const uint32_t (&a)[4], const uint32_t (&b)[2]) {
    asm volatile("mma.sync.aligned.m16n8k16.row.col.f32.f16.f16.f32 "
                 "{%0,%1,%2,%3}, {%4,%5,%6,%7}, {%8,%9}, {%0,%1,%2,%3};"
                 : "+f"(c[0]), "+f"(c[1]), "+f"(c[2]), "+f"(c[3])
                 : "r"(a[0]), "r"(a[1]), "r"(a[2]), "r"(a[3]), "r"(b[0]), "r"(b[1]));
}
__device__ __forceinline__ void cp16(uint32_t dst, const void* src) {
    asm volatile("cp.async.cg.shared.global [%0], [%1], 16;" :: "r"(dst), "l"(src));
}
#define CP_COMMIT() asm volatile("cp.async.commit_group;" ::: "memory")
#define CP_WAIT1()  asm volatile("cp.async.wait_group 1;" ::: "memory")
#define CP_WAIT0()  asm volatile("cp.async.wait_group 0;" ::: "memory")

__device__ __forceinline__ uint32_t cvt_bf2(float lo, float hi) {
    uint32_t r;
    asm("cvt.rn.bf16x2.f32 %0, %1, %2;" : "=r"(r) : "f"(hi), "f"(lo));
    return r;
}

template<int DT> struct Elem    { using T = __nv_bfloat16; };
template<>       struct Elem<1> { using T = __half; };

template<int DT>
__device__ __forceinline__ void mma_t(float (&c)[4], const uint32_t (&a)[4], const uint32_t (&b)[2]) {
    if constexpr (DT == 0) mma_bf16(c, a, b); else mma_f16(c, a, b);
}
template<int DT>
__device__ __forceinline__ uint32_t pack_t(float x, float y) {
    if constexpr (DT == 0) {
        return cvt_bf2(x, y);
    } else {
        __half2 h = __floats2half2_rn(x, y);
        return *(uint32_t*)&h;
    }
}

// ---------------------------------------------------------------- LayerNorm -> T
template<int DT>
__global__ void ln_kernel(const float* __restrict__ x,
                          typename Elem<DT>::T* __restrict__ hi,
                          const float* __restrict__ alpha_p, const float* __restrict__ bias_p)
{
    const int row = blockIdx.x;
    const float* xr = x + (size_t)row * DD;
    const int tid = threadIdx.x, lane = tid & 31, wid = tid >> 5;
    __shared__ float red[8];
    __shared__ float s_mean, s_scale;

    float s = 0.f;
    for (int i = tid; i < DD; i += 256) s += xr[i];
    #pragma unroll
    for (int o = 16; o; o >>= 1) s += __shfl_xor_sync(0xffffffffu, s, o);
    if (lane == 0) red[wid] = s;
    __syncthreads();
    if (tid == 0) {
        float t = 0.f;
        #pragma unroll
        for (int i = 0; i < 8; i++) t += red[i];
        s_mean = t / (float)DD;
    }
    __syncthreads();
    const float mean = s_mean;

    float vs = 0.f;
    for (int i = tid; i < DD; i += 256) { float d = xr[i] - mean; vs += d * d; }
    #pragma unroll
    for (int o = 16; o; o >>= 1) vs += __shfl_xor_sync(0xffffffffu, vs, o);
    if (lane == 0) red[wid] = vs;
    __syncthreads();
    if (tid == 0) {
        float t = 0.f;
        #pragma unroll
        for (int i = 0; i < 8; i++) t += red[i];
        s_scale = alpha_p[0] / (sqrtf(t / (float)(DD - 1)) + 1e-6f);
    }
    __syncthreads();
    const float scale = s_scale, bias = bias_p[0];

    for (int i = tid; i < DD; i += 256) {
        float y = (xr[i] - mean) * scale + bias;
        if constexpr (DT == 0) hi[(size_t)row * DD + i] = __float2bfloat16(y);
        else                   hi[(size_t)row * DD + i] = __float2half(y);
    }
}

// ---------------------------------------------------------------- fused weight transpose (mixed dtype)
struct WSArgs {
    const float* W[6];
    void* Hi[6];
    int dt[6];
    int Kd[6], Nd[6];
    int start[7];
};

__global__ void ws_all(WSArgs a)
{
    __shared__ float t[32][33];
    int bidx = blockIdx.x;
    int e = 0;
    while (bidx >= a.start[e + 1]) e++;
    const int rel = bidx - a.start[e];
    const int Kd = a.Kd[e], Nd = a.Nd[e];
    const int nx = Nd / 32;
    const int n0 = (rel % nx) * 32, k0 = (rel / nx) * 32;
    const float* W = a.W[e];
    void* Hi = a.Hi[e];
    const int dt = a.dt[e];

    const int tx = threadIdx.x, ty = threadIdx.y;   // 32x8
    #pragma unroll
    for (int r = 0; r < 4; r++)
        t[ty + 8 * r][tx] = W[(size_t)(k0 + ty + 8 * r) * Nd + n0 + tx];
    __syncthreads();
    #pragma unroll
    for (int r = 0; r < 4; r++) {
        float v = t[tx][ty + 8 * r];
        size_t o = (size_t)(n0 + ty + 8 * r) * Kd + k0 + tx;
        if (dt == 0) ((__nv_bfloat16*)Hi)[o] = __float2bfloat16(v);
        else         ((__half*)Hi)[o]        = __float2half(v);
    }
}

// ---------------------------------------------------------------- HMMA GEMM: 128x256 CTA tile, 8 warps (2M x 4N), warp 64x64
// 2-stage K64 pipeline. C = A @ B^T, B given [N,K]; DT: 0=bf16, 1=fp16.
struct GemmArgs {
    const void *A;
    const void *B0, *B1, *B2;
    float *C0, *C1, *C2;
    const float *bias, *res;
    void *S0, *S1, *S2;          // optional T outputs
    int relu, N, K;
};

#define GP 144                         // row pitch bytes for 64-elem (128B) rows
#define GATILE (128 * GP)              // 18432 (A: 128 rows)
#define GBTILE (256 * GP)              // 36864 (B: 256 rows)
#define GSTG   (GATILE + GBTILE)       // 55296 per stage
#define GSMEM  (2 * GSTG)              // 110592 (2 stages)

template<int DT>
__global__ void __launch_bounds__(256, 1) mma_gemm(GemmArgs ga)
{
    using T = typename Elem<DT>::T;
    extern __shared__ char smc[];
    const uint32_t smb = smem_to_u32(smc);
    const int tid = threadIdx.x, wid = tid >> 5, lane = tid & 31;
    const int bn = blockIdx.x * 256, bm = blockIdx.y * 128;
    const int z = blockIdx.z;
    const T* A = (const T*)ga.A;
    const T* B = (const T*)((z == 0) ? ga.B0 : ((z == 1) ? ga.B1 : ga.B2));
    float* C = (z == 0) ? ga.C0 : ((z == 1) ? ga.C1 : ga.C2);
    T* Sh = (T*)((z == 0) ? ga.S0 : ((z == 1) ? ga.S1 : ga.S2));
    const int K = ga.K, NC = K / 64;

    const int wm64 = (wid & 1) * 64;       // 2 warps over M (128)
    const int wn64 = (wid >> 1) * 64;      // 4 warps over N (256)

    float acc[4][8][4];
    #pragma unroll
    for (int f = 0; f < 4; f++)
        #pragma unroll
        for (int n = 0; n < 8; n++)
            #pragma unroll
            for (int e = 0; e < 4; e++) acc[f][n][e] = 0.f;

    auto issue = [&](int c) {
        const int ks = c * 64;
        const uint32_t base = smb + (uint32_t)(c & 1) * GSTG;
        // 3072 lanes: 0..1023 A (128 rows x 8), 1024..3071 B (256 rows x 8)
        #pragma unroll
        for (int i = 0; i < 12; i++) {
            const int u = tid + i * 256;
            const int c16 = u & 7;
            if (u < 1024) {
                const int row = u >> 3;
                cp16(base + row * GP + c16 * 16,
                     A + (size_t)(bm + row) * K + ks + c16 * 8);
            } else {
                const int row = (u - 1024) >> 3;
                cp16(base + GATILE + row * GP + c16 * 16,
                     B + (size_t)(bn + row) * K + ks + c16 * 8);
            }
        }
        CP_COMMIT();
    };

    issue(0);
    if (NC > 1) issue(1);

    const uint32_t aBase0 = smb + (uint32_t)((wm64 + (lane & 15)) * GP + ((lane >> 4) << 3) * 2);
    const uint32_t bBase0 = smb + (uint32_t)GATILE
                          + (uint32_t)((wn64 + ((lane >> 4) << 3) + (lane & 7)) * GP
                                       + (((lane >> 3) & 1) << 3) * 2);

    for (int c = 0; c < NC; c++) {
        if (c + 1 < NC) { CP_WAIT1(); } else { CP_WAIT0(); }
        __syncthreads();

        const uint32_t stg = (uint32_t)(c & 1) * GSTG;
        uint32_t aAddr = aBase0 + stg;
        uint32_t bAddr = bBase0 + stg;
        #pragma unroll
        for (int kk = 0; kk < 4; kk++) {
            uint32_t af[4][4];
            #pragma unroll
            for (int f = 0; f < 4; f++)
                ldsm_x4(af[f], aAddr + (uint32_t)(f * 16 * GP));
            uint32_t bq[4][4];
            #pragma unroll
            for (int p = 0; p < 4; p++)
                ldsm_x4(bq[p], bAddr + (uint32_t)(p * 16 * GP));
            aAddr += 32;
            bAddr += 32;
            #pragma unroll
            for (int f = 0; f < 4; f++) {
                #pragma unroll
                for (int p = 0; p < 4; p++) {
                    uint32_t b0[2] = { bq[p][0], bq[p][1] };
                    uint32_t b1[2] = { bq[p][2], bq[p][3] };
                    mma_t<DT>(acc[f][2 * p],     af[f], b0);
                    mma_t<DT>(acc[f][2 * p + 1], af[f], b1);
                }
            }
        }
        __syncthreads();                     // buffer (c&1) free for reuse
        if (c + 2 < NC) issue(c + 2);
    }

    // ---- epilogue
    const int gq = lane >> 2, t4 = lane & 3;
    #pragma unroll
    for (int f = 0; f < 4; f++) {
        #pragma unroll
        for (int half = 0; half < 2; half++) {
            const int m = bm + wm64 + f * 16 + gq + half * 8;
            const size_t rowo = (size_t)m * ga.N;
            #pragma unroll
            for (int n = 0; n < 8; n++) {
                const int col = bn + wn64 + n * 8 + t4 * 2;
                float vx = acc[f][n][half * 2 + 0];
                float vy = acc[f][n][half * 2 + 1];
                if (ga.bias) {
                    float2 bb = *(const float2*)(ga.bias + col);
                    vx += bb.x; vy += bb.y;
                }
                if (ga.relu) { vx = fmaxf(vx, 0.f); vy = fmaxf(vy, 0.f); }
                if (ga.res) {
                    float2 rr = *(const float2*)(ga.res + rowo + col);
                    vx += rr.x; vy += rr.y;
                }
                if (Sh) {
                    *(uint32_t*)(Sh + rowo + col) = pack_t<DT>(vx, vy);
                } else {
                    *(float2*)(C + rowo + col) = make_float2(vx, vy);
                }
            }
        }
    }
}

// ---------------------------------------------------------------- HMMA flash attention (bf16)
// 256 threads, 8 warps x 32 queries = 256 queries/CTA; K/V 64-key tiles, 2-stage.
#define FPITCH 144
#define FQOFF 0
#define FQSZ  (256 * FPITCH)                 // 36864
#define FKOFF FQSZ
#define FSTG  (2 * 64 * FPITCH)              // 18432 (K + V per stage)
#define FMOFF (FKOFF + 2 * FSTG)             // 73728
#define FSMEM (FMOFF + 512)                  // 74240

__global__ void __launch_bounds__(256, 1) flash_mma(
    const __nv_bfloat16* __restrict__ Qb, const __nv_bfloat16* __restrict__ Kb,
    const __nv_bfloat16* __restrict__ Vb, const int* __restrict__ mask,
    __nv_bfloat16* __restrict__ Ohi)
{
    extern __shared__ char fsm[];
    const uint32_t smb = smem_to_u32(fsm);
    const int tid = threadIdx.x, wid = tid >> 5, lane = tid & 31;
    const int gq = lane >> 2, t4 = lane & 3;
    const int bh = blockIdx.x, b = bh / HH, h = bh % HH;
    const int q0 = blockIdx.y * 256;
    const int NIT = SS / 64;

    auto cpKV = [&](int it, int st) {
        const uint32_t ks = smb + FKOFF + st * FSTG;
        const uint32_t vs = ks + 64 * FPITCH;
        const __nv_bfloat16* Ksrc = Kb + (size_t)(b * SS + it * 64) * DD + h * 64;
        const __nv_bfloat16* Vsrc = Vb + (size_t)(b * SS + it * 64) * DD + h * 64;
        #pragma unroll
        for (int i = 0; i < 2; i++) {
            const int idx = tid + i * 256;                 // 0..511
            const int r = idx >> 3, c = idx & 7;
            cp16(ks + r * FPITCH + c * 16, Ksrc + (size_t)r * DD + c * 8);
            cp16(vs + r * FPITCH + c * 16, Vsrc + (size_t)r * DD + c * 8);
        }
        if (tid < 16)
            cp16(smb + FMOFF + st * 256 + tid * 16, mask + b * SS + it * 64 + tid * 4);
        CP_COMMIT();
    };

    {
        const __nv_bfloat16* Qsrc = Qb + (size_t)(b * SS + q0) * DD + h * 64;
        #pragma unroll
        for (int i = 0; i < 8; i++) {
            const int idx = tid + i * 256;                 // 0..2047
            const int r = idx >> 3, c = idx & 7;
            cp16(smb + FQOFF + r * FPITCH + c * 16, Qsrc + (size_t)r * DD + c * 8);
        }
        // stage 0 K/V + mask in the same cp group as Q
        const uint32_t ks = smb + FKOFF;
        const uint32_t vs = ks + 64 * FPITCH;
        const __nv_bfloat16* Ksrc = Kb + (size_t)(b * SS) * DD + h * 64;
        const __nv_bfloat16* Vsrc = Vb + (size_t)(b * SS) * DD + h * 64;
        #pragma unroll
        for (int i = 0; i < 2; i++) {
            const int idx = tid + i * 256;
            const int r = idx >> 3, c = idx & 7;
            cp16(ks + r * FPITCH + c * 16, Ksrc + (size_t)r * DD + c * 8);
            cp16(vs + r * FPITCH + c * 16, Vsrc + (size_t)r * DD + c * 8);
        }
        if (tid < 16)
            cp16(smb + FMOFF + tid * 16, mask + b * SS + tid * 4);
        CP_COMMIT();
        cpKV(1, 1);
    }

    CP_WAIT1();
    __syncthreads();

    // Q fragments: warp owns rows wid*32 .. wid*32+31 (2 m16 sets)
    uint32_t aq[2][4][4];
    #pragma unroll
    for (int s = 0; s < 2; s++)
        #pragma unroll
        for (int kc = 0; kc < 4; kc++) {
            uint32_t addr = smb + FQOFF
                          + (uint32_t)((wid * 32 + s * 16 + (lane & 15)) * FPITCH
                                       + (kc * 16 + ((lane >> 4) << 3)) * 2);
            ldsm_x4(aq[s][kc], addr);
        }

    float oacc[2][8][4];
    #pragma unroll
    for (int s = 0; s < 2; s++)
        #pragma unroll
        for (int n = 0; n < 8; n++)
            #pragma unroll
            for (int e = 0; e < 4; e++) oacc[s][n][e] = 0.f;
    float lsum[2][2] = {{0.f, 0.f}, {0.f, 0.f}};

    for (int it = 0; it < NIT; it++) {
        if (it > 0) {
            if (it + 1 < NIT) { CP_WAIT1(); } else { CP_WAIT0(); }
            __syncthreads();
        }
        const int st = it & 1;
        const uint32_t ks = smb + FKOFF + st * FSTG;
        const uint32_t vs = ks + 64 * FPITCH;
        const int* Mi = (const int*)(fsm + FMOFF + st * 256);

        // ---- S = Q @ K^T  (two 16-row sets share every K fragment)
        float sacc[2][8][4];
        #pragma unroll
        for (int s = 0; s < 2; s++)
            #pragma unroll
            for (int j = 0; j < 8; j++)
                #pragma unroll
                for (int e = 0; e < 4; e++) sacc[s][j][e] = 0.f;

        #pragma unroll
        for (int kc = 0; kc < 4; kc++) {
            uint32_t bfr[4][4];
            #pragma unroll
            for (int jj = 0; jj < 4; jj++) {
                uint32_t addr = ks + (uint32_t)((jj * 16 + ((lane >> 4) << 3) + (lane & 7)) * FPITCH
                                                + (kc * 16 + (((lane >> 3) & 1) << 3)) * 2);
                ldsm_x4(bfr[jj], addr);
            }
            #pragma unroll
            for (int jj = 0; jj < 4; jj++) {
                uint32_t b0[2] = { bfr[jj][0], bfr[jj][1] };
                uint32_t b1[2] = { bfr[jj][2], bfr[jj][3] };
                #pragma unroll
                for (int s = 0; s < 2; s++) {
                    mma_bf16(sacc[s][2 * jj],     aq[s][kc], b0);
                    mma_bf16(sacc[s][2 * jj + 1], aq[s][kc], b1);
                }
            }
        }

        // ---- mask + scale + exp; pack P to bf16 frags
        uint32_t pf[2][8][2];
        #pragma unroll
        for (int s = 0; s < 2; s++) {
            #pragma unroll
            for (int j = 0; j < 8; j++) {
                const int col = j * 8 + t4 * 2;
                const int m0 = Mi[col], m1 = Mi[col + 1];
                float s0 = m0 ? sacc[s][j][0] * 0.125f : 1e-9f;
                float s1 = m1 ? sacc[s][j][1] * 0.125f : 1e-9f;
                float s2 = m0 ? sacc[s][j][2] * 0.125f : 1e-9f;
                float s3 = m1 ? sacc[s][j][3] * 0.125f : 1e-9f;
                float p0 = __expf(s0), p1 = __expf(s1), p2 = __expf(s2), p3 = __expf(s3);
                lsum[s][0] += p0 + p1;
                lsum[s][1] += p2 + p3;
                pf[s][j][0] = cvt_bf2(p0, p1);
                pf[s][j][1] = cvt_bf2(p2, p3);
            }
        }

        // ---- O += P @ V  (two sets share every V fragment)
        #pragma unroll
        for (int jk = 0; jk < 4; jk++) {
            #pragma unroll
            for (int nn = 0; nn < 4; nn++) {
                uint32_t bv[4];
                uint32_t addr = vs + (uint32_t)((jk * 16 + (((lane >> 3) & 1) << 3) + (lane & 7)) * FPITCH
                                                + (nn * 16 + ((lane >> 4) << 3)) * 2);
                ldsm_x4_t(bv, addr);
                uint32_t b0[2] = { bv[0], bv[1] };
                uint32_t b1[2] = { bv[2], bv[3] };
                #pragma unroll
                for (int s = 0; s < 2; s++) {
                    uint32_t a[4] = { pf[s][2 * jk][0], pf[s][2 * jk][1],
                                      pf[s][2 * jk + 1][0], pf[s][2 * jk + 1][1] };
                    mma_bf16(oacc[s][2 * nn],     a, b0);
                    mma_bf16(oacc[s][2 * nn + 1], a, b1);
                }
            }
        }

        __syncthreads();
        if (it + 2 < NIT) cpKV(it + 2, st);
    }

    #pragma unroll
    for (int s = 0; s < 2; s++) {
        lsum[s][0] += __shfl_xor_sync(0xffffffffu, lsum[s][0], 1);
        lsum[s][0] += __shfl_xor_sync(0xffffffffu, lsum[s][0], 2);
        lsum[s][1] += __shfl_xor_sync(0xffffffffu, lsum[s][1], 1);
        lsum[s][1] += __shfl_xor_sync(0xffffffffu, lsum[s][1], 2);
        const float inv0 = 1.f / lsum[s][0], inv1 = 1.f / lsum[s][1];
        const int r0 = b * SS + q0 + wid * 32 + s * 16 + gq;
        const int r1 = r0 + 8;
        #pragma unroll
        for (int nn = 0; nn < 8; nn++) {
            const int col = h * 64 + nn * 8 + t4 * 2;
            *(uint32_t*)(Ohi + (size_t)r0 * DD + col) =
                cvt_bf2(oacc[s][nn][0] * inv0, oacc[s][nn][1] * inv0);
            *(uint32_t*)(Ohi + (size_t)r1 * DD + col) =
                cvt_bf2(oacc[s][nn][2] * inv1, oacc[s][nn][3] * inv1);
        }
    }
}

// ---------------------------------------------------------------- launch
extern "C" void kernel_launch(void* const* d_in, const int* in_sizes, int n_in,
                              void* d_out, int out_size)
{
    const float* x    = (const float*)d_in[0];
    const int*   mask = (const int*)  d_in[1];
    const float* wq   = (const float*)d_in[2];
    const float* wk   = (const float*)d_in[3];
    const float* wv   = (const float*)d_in[4];
    const float* wo   = (const float*)d_in[5];
    const float* w1   = (const float*)d_in[6];
    const float* b1   = (const float*)d_in[7];
    const float* w2   = (const float*)d_in[8];
    const float* b2   = (const float*)d_in[9];
    const float* ln1a = (const float*)d_in[10];
    const float* ln1b = (const float*)d_in[11];
    const float* ln2a = (const float*)d_in[12];
    const float* ln2b = (const float*)d_in[13];
    float* out = (float*)d_out;

    __nv_bfloat16 *thi, *chi, *qb, *kb, *vb;
    __nv_bfloat16 *wqhi, *wkhi, *wvhi, *wohi;
    __half *t16, *h1, *w1h, *w2h;
    float *x2;
    cudaGetSymbolAddress((void**)&thi, g_thi);
    cudaGetSymbolAddress((void**)&t16, g_t16);
    cudaGetSymbolAddress((void**)&chi, g_chi);
    cudaGetSymbolAddress((void**)&h1, g_h1);
    cudaGetSymbolAddress((void**)&qb, g_qb);     cudaGetSymbolAddress((void**)&kb, g_kb);
    cudaGetSymbolAddress((void**)&vb, g_vb);
    cudaGetSymbolAddress((void**)&wqhi, g_wqhi);
    cudaGetSymbolAddress((void**)&wkhi, g_wkhi);
    cudaGetSymbolAddress((void**)&wvhi, g_wvhi);
    cudaGetSymbolAddress((void**)&wohi, g_wohi);
    cudaGetSymbolAddress((void**)&w1h, g_w1h);
    cudaGetSymbolAddress((void**)&w2h, g_w2h);
    cudaGetSymbolAddress((void**)&x2, g_x2);

    cudaFuncSetAttribute(mma_gemm<0>, cudaFuncAttributeMaxDynamicSharedMemorySize, GSMEM);
    cudaFuncSetAttribute(mma_gemm<1>, cudaFuncAttributeMaxDynamicSharedMemorySize, GSMEM);
    cudaFuncSetAttribute(flash_mma, cudaFuncAttributeMaxDynamicSharedMemorySize, FSMEM);

    // fused weight transpose (bf16 for q/k/v/o; fp16 for w1/w2)
    WSArgs wa = {};
    wa.W[0] = wq; wa.Hi[0] = wqhi; wa.dt[0] = 0; wa.Kd[0] = DD; wa.Nd[0] = DD;
    wa.W[1] = wk; wa.Hi[1] = wkhi; wa.dt[1] = 0; wa.Kd[1] = DD; wa.Nd[1] = DD;
    wa.W[2] = wv; wa.Hi[2] = wvhi; wa.dt[2] = 0; wa.Kd[2] = DD; wa.Nd[2] = DD;
    wa.W[3] = wo; wa.Hi[3] = wohi; wa.dt[3] = 0; wa.Kd[3] = DD; wa.Nd[3] = DD;
    wa.W[4] = w1; wa.Hi[4] = w1h;  wa.dt[4] = 1; wa.Kd[4] = DD; wa.Nd[4] = FF;
    wa.W[5] = w2; wa.Hi[5] = w2h;  wa.dt[5] = 1; wa.Kd[5] = FF; wa.Nd[5] = DD;
    int acc0 = 0;
    wa.start[0] = 0;
    for (int e = 0; e < 6; e++) {
        acc0 += (wa.Nd[e] / 32) * (wa.Kd[e] / 32);
        wa.start[e + 1] = acc0;
    }
    ws_all<<<acc0, dim3(32, 8)>>>(wa);

    // LN1 -> bf16
    ln_kernel<0><<<NROW, 256>>>(x, thi, ln1a, ln1b);

    // Q/K/V projections (bf16, z-batched), N-tiles of 256
    GemmArgs aq = {};
    aq.A = thi;
    aq.B0 = wqhi; aq.B1 = wkhi; aq.B2 = wvhi;
    aq.S0 = qb; aq.S1 = kb; aq.S2 = vb;
    aq.N = DD; aq.K = DD;
    mma_gemm<0><<<dim3(DD / 256, NROW / 128, 3), 256, GSMEM>>>(aq);

    // attention -> bf16 context (256 queries / CTA)
    flash_mma<<<dim3(BB * HH, SS / 256), 256, FSMEM>>>(qb, kb, vb, mask, chi);

    // x2 = x + ctx @ wo (bf16)
    GemmArgs ao = {};
    ao.A = chi;
    ao.B0 = wohi;
    ao.C0 = x2;
    ao.res = x;
    ao.N = DD; ao.K = DD;
    mma_gemm<0><<<dim3(DD / 256, NROW / 128, 1), 256, GSMEM>>>(ao);

    // LN2 -> fp16
    ln_kernel<1><<<NROW, 256>>>(x2, t16, ln2a, ln2b);

    // FFN1: h1 = relu(t @ w1 + b1) (fp16)
    GemmArgs a1 = {};
    a1.A = t16;
    a1.B0 = w1h;
    a1.bias = b1; a1.relu = 1;
    a1.S0 = h1;
    a1.N = FF; a1.K = DD;
    mma_gemm<1><<<dim3(FF / 256, NROW / 128, 1), 256, GSMEM>>>(a1);

    // FFN2: out = x2 + h1 @ w2 + b2 (fp16)
    GemmArgs a2 = {};
    a2.A = h1;
    a2.B0 = w2h;
    a2.C0 = out;
    a2.bias = b2; a2.res = x2;
    a2.N = DD; a2.K = FF;
    mma_gemm<1><<<dim3(DD / 256, NROW / 128, 1), 256, GSMEM>>>(a2);
}

// round 12
// speedup vs baseline: 1.1904x; 1.1904x over previous
#include <cuda_runtime.h>
#include <cuda_bf16.h>
#include <cuda_fp16.h>
#include <cstdint>
#include <math.h>

#define BB 2
#define SS 2048
#define DD 768
#define FF 3072
#define HH 12
#define DKK 64
#define NROW (BB*SS)   // 4096

// ---------------------------------------------------------------- scratch
__device__ __nv_bfloat16 g_thi[NROW*DD];
__device__ __half        g_t16[NROW*DD];
__device__ __nv_bfloat16 g_qb[NROW*DD], g_kb[NROW*DD], g_vb[NROW*DD];
__device__ float g_x2[NROW*DD];
__device__ __nv_bfloat16 g_chi[NROW*DD];
__device__ __half        g_h1[NROW*FF];
__device__ __nv_bfloat16 g_wqhi[DD*DD];
__device__ __nv_bfloat16 g_wkhi[DD*DD];
__device__ __nv_bfloat16 g_wvhi[DD*DD];
__device__ __nv_bfloat16 g_wohi[DD*DD];
__device__ __half        g_w1h[FF*DD];   // [F,D] = w1^T (fp16)
__device__ __half        g_w2h[DD*FF];   // [D,F] = w2^T (fp16)

// ---------------------------------------------------------------- helpers
__device__ __forceinline__ uint32_t smem_to_u32(const void* p) {
    uint32_t a;
    asm("{ .reg .u64 t; cvta.to.shared.u64 t, %1; cvt.u32.u64 %0, t; }" : "=r"(a) : "l"(p));
    return a;
}
__device__ __forceinline__ void ldsm_x4(uint32_t (&r)[4], uint32_t addr) {
    asm volatile("ldmatrix.sync.aligned.m8n8.x4.shared.b16 {%0,%1,%2,%3}, [%4];"
                 : "=r"(r[0]), "=r"(r[1]), "=r"(r[2]), "=r"(r[3]) : "r"(addr));
}
__device__ __forceinline__ void ldsm_x4_t(uint32_t (&r)[4], uint32_t addr) {
    asm volatile("ldmatrix.sync.aligned.m8n8.x4.trans.shared.b16 {%0,%1,%2,%3}, [%4];"
                 : "=r"(r[0]), "=r"(r[1]), "=r"(r[2]), "=r"(r[3]) : "r"(addr));
}
__device__ __forceinline__ void mma_bf16(float (&c)[4], const uint32_t (&a)[4], const uint32_t (&b)[2]) {
    asm volatile("mma.sync.aligned.m16n8k16.row.col.f32.bf16.bf16.f32 "
                 "{%0,%1,%2,%3}, {%4,%5,%6,%7}, {%8,%9}, {%0,%1,%2,%3};"
                 : "+f"(c[0]), "+f"(c[1]), "+f"(c[2]), "+f"(c[3])
                 : "r"(a[0]), "r"(a[1]), "r"(a[2]), "r"(a[3]), "r"(b[0]), "r"(b[1]));
}
__device__ __forceinline__ void mma_f16(float (&c)[4], const uint32_t (&a)[4], const uint32_t (&b)[2]) {
    asm volatile("mma.sync.aligned.m16n8k16.row.col.f32.f16.f16.f32 "
                 "{%0,%1,%2,%3}, {%4,%5,%6,%7}, {%8,%9}, {%0,%1,%2,%3};"
                 : "+f"(c[0]), "+f"(c[1]), "+f"(c[2]), "+f"(c[3])
                 : "r"(a[0]), "r"(a[1]), "r"(a[2]), "r"(a[3]), "r"(b[0]), "r"(b[1]));
}
__device__ __forceinline__ void cp16(uint32_t dst, const void* src) {
    asm volatile("cp.async.cg.shared.global [%0], [%1], 16;" :: "r"(dst), "l"(src));
}
#define CP_COMMIT() asm volatile("cp.async.commit_group;" ::: "memory")
#define CP_WAIT1()  asm volatile("cp.async.wait_group 1;" ::: "memory")
#define CP_WAIT0()  asm volatile("cp.async.wait_group 0;" ::: "memory")

__device__ __forceinline__ uint32_t cvt_bf2(float lo, float hi) {
    uint32_t r;
    asm("cvt.rn.bf16x2.f32 %0, %1, %2;" : "=r"(r) : "f"(hi), "f"(lo));
    return r;
}

template<int DT> struct Elem    { using T = __nv_bfloat16; };
template<>       struct Elem<1> { using T = __half; };

template<int DT>
__device__ __forceinline__ void mma_t(float (&c)[4], const uint32_t (&a)[4], const uint32_t (&b)[2]) {
    if constexpr (DT == 0) mma_bf16(c, a, b); else mma_f16(c, a, b);
}
template<int DT>
__device__ __forceinline__ uint32_t pack_t(float x, float y) {
    if constexpr (DT == 0) {
        return cvt_bf2(x, y);
    } else {
        __half2 h = __floats2half2_rn(x, y);
        return *(uint32_t*)&h;
    }
}

// ---------------------------------------------------------------- LayerNorm -> T
template<int DT>
__global__ void ln_kernel(const float* __restrict__ x,
                          typename Elem<DT>::T* __restrict__ hi,
                          const float* __restrict__ alpha_p, const float* __restrict__ bias_p)
{
    const int row = blockIdx.x;
    const float* xr = x + (size_t)row * DD;
    const int tid = threadIdx.x, lane = tid & 31, wid = tid >> 5;
    __shared__ float red[8];
    __shared__ float s_mean, s_scale;

    float s = 0.f;
    for (int i = tid; i < DD; i += 256) s += xr[i];
    #pragma unroll
    for (int o = 16; o; o >>= 1) s += __shfl_xor_sync(0xffffffffu, s, o);
    if (lane == 0) red[wid] = s;
    __syncthreads();
    if (tid == 0) {
        float t = 0.f;
        #pragma unroll
        for (int i = 0; i < 8; i++) t += red[i];
        s_mean = t / (float)DD;
    }
    __syncthreads();
    const float mean = s_mean;

    float vs = 0.f;
    for (int i = tid; i < DD; i += 256) { float d = xr[i] - mean; vs += d * d; }
    #pragma unroll
    for (int o = 16; o; o >>= 1) vs += __shfl_xor_sync(0xffffffffu, vs, o);
    if (lane == 0) red[wid] = vs;
    __syncthreads();
    if (tid == 0) {
        float t = 0.f;
        #pragma unroll
        for (int i = 0; i < 8; i++) t += red[i];
        s_scale = alpha_p[0] / (sqrtf(t / (float)(DD - 1)) + 1e-6f);
    }
    __syncthreads();
    const float scale = s_scale, bias = bias_p[0];

    for (int i = tid; i < DD; i += 256) {
        float y = (xr[i] - mean) * scale + bias;
        if constexpr (DT == 0) hi[(size_t)row * DD + i] = __float2bfloat16(y);
        else                   hi[(size_t)row * DD + i] = __float2half(y);
    }
}

// ---------------------------------------------------------------- fused weight transpose (mixed dtype)
struct WSArgs {
    const float* W[6];
    void* Hi[6];
    int dt[6];
    int Kd[6], Nd[6];
    int start[7];
};

__global__ void ws_all(WSArgs a)
{
    __shared__ float t[32][33];
    int bidx = blockIdx.x;
    int e = 0;
    while (bidx >= a.start[e + 1]) e++;
    const int rel = bidx - a.start[e];
    const int Kd = a.Kd[e], Nd = a.Nd[e];
    const int nx = Nd / 32;
    const int n0 = (rel % nx) * 32, k0 = (rel / nx) * 32;
    const float* W = a.W[e];
    void* Hi = a.Hi[e];
    const int dt = a.dt[e];

    const int tx = threadIdx.x, ty = threadIdx.y;   // 32x8
    #pragma unroll
    for (int r = 0; r < 4; r++)
        t[ty + 8 * r][tx] = W[(size_t)(k0 + ty + 8 * r) * Nd + n0 + tx];
    __syncthreads();
    #pragma unroll
    for (int r = 0; r < 4; r++) {
        float v = t[tx][ty + 8 * r];
        size_t o = (size_t)(n0 + ty + 8 * r) * Kd + k0 + tx;
        if (dt == 0) ((__nv_bfloat16*)Hi)[o] = __float2bfloat16(v);
        else         ((__half*)Hi)[o]        = __float2half(v);
    }
}

// ---------------------------------------------------------------- HMMA GEMM: 8 warps, warp tile 64x32, 2-stage K64
// C = A @ B^T, B given [N,K]; DT: 0=bf16, 1=fp16. 16 warps/SM via 2 CTAs.
// splitk > 1: blockIdx.z indexes a K-partition; partials atomicAdd into
// zero-initialized C; partition 0 carries bias (+res).
struct GemmArgs {
    const void *A;
    const void *B0, *B1, *B2;
    float *C0, *C1, *C2;
    const float *bias, *res;
    void *S0, *S1, *S2;          // optional T outputs (not valid with splitk)
    int relu, N, K, splitk;
};

#define GP 144                        // row pitch bytes for 64-elem (128B) rows
#define GTILE (128 * GP)              // 18432
#define GSTG  (2 * GTILE)             // 36864 (A + B)
#define GSMEM (2 * GSTG)              // 73728 (2 stages)

template<int DT>
__global__ void __launch_bounds__(256, 2) mma_gemm(GemmArgs ga)
{
    using T = typename Elem<DT>::T;
    extern __shared__ char smc[];
    const uint32_t smb = smem_to_u32(smc);
    const int tid = threadIdx.x, wid = tid >> 5, lane = tid & 31;
    const int bn = blockIdx.x * 128, bm = blockIdx.y * 128;
    const int z = blockIdx.z;
    const int sk = ga.splitk;
    const T* A = (const T*)ga.A;
    const T* B; float* C; T* Sh;
    int c0, NC;
    if (sk > 1) {
        B = (const T*)ga.B0; C = ga.C0; Sh = nullptr;
        NC = ga.K / 64 / sk;
        c0 = z * NC;
    } else {
        B = (const T*)((z == 0) ? ga.B0 : ((z == 1) ? ga.B1 : ga.B2));
        C = (z == 0) ? ga.C0 : ((z == 1) ? ga.C1 : ga.C2);
        Sh = (T*)((z == 0) ? ga.S0 : ((z == 1) ? ga.S1 : ga.S2));
        NC = ga.K / 64;
        c0 = 0;
    }
    const int K = ga.K;

    const int wm64 = (wid & 1) * 64;       // 2 warps over M
    const int wn32 = (wid >> 1) * 32;      // 4 warps over N

    float acc[4][4][4];
    #pragma unroll
    for (int f = 0; f < 4; f++)
        #pragma unroll
        for (int n = 0; n < 4; n++)
            #pragma unroll
            for (int e = 0; e < 4; e++) acc[f][n][e] = 0.f;

    auto issue = [&](int c) {
        const int ks = (c0 + c) * 64;
        const uint32_t base = smb + (uint32_t)(c & 1) * GSTG;
        #pragma unroll
        for (int i = 0; i < 8; i++) {
            const int u = tid + i * 256;                 // 0..2047
            const int row = (u >> 3) & 127, c16 = u & 7;
            const uint32_t dst = base + ((u < 1024) ? 0u : (uint32_t)GTILE)
                               + row * GP + c16 * 16;
            const T* src = (u < 1024)
                ? (A + (size_t)(bm + row) * K + ks + c16 * 8)
                : (B + (size_t)(bn + row) * K + ks + c16 * 8);
            cp16(dst, src);
        }
        CP_COMMIT();
    };

    issue(0);
    if (NC > 1) issue(1);

    const uint32_t aBase0 = smb + (uint32_t)((wm64 + (lane & 15)) * GP + ((lane >> 4) << 3) * 2);
    const uint32_t bBase0 = smb + (uint32_t)GTILE
                          + (uint32_t)((wn32 + ((lane >> 4) << 3) + (lane & 7)) * GP
                                       + (((lane >> 3) & 1) << 3) * 2);

    for (int c = 0; c < NC; c++) {
        if (c + 1 < NC) { CP_WAIT1(); } else { CP_WAIT0(); }
        __syncthreads();

        const uint32_t stg = (uint32_t)(c & 1) * GSTG;
        uint32_t aAddr = aBase0 + stg;
        uint32_t bAddr = bBase0 + stg;
        #pragma unroll
        for (int kk = 0; kk < 4; kk++) {
            uint32_t af[4][4];
            #pragma unroll
            for (int f = 0; f < 4; f++)
                ldsm_x4(af[f], aAddr + (uint32_t)(f * 16 * GP));
            uint32_t bq[2][4];
            #pragma unroll
            for (int p = 0; p < 2; p++)
                ldsm_x4(bq[p], bAddr + (uint32_t)(p * 16 * GP));
            aAddr += 32;
            bAddr += 32;
            #pragma unroll
            for (int f = 0; f < 4; f++) {
                #pragma unroll
                for (int p = 0; p < 2; p++) {
                    uint32_t b0[2] = { bq[p][0], bq[p][1] };
                    uint32_t b1[2] = { bq[p][2], bq[p][3] };
                    mma_t<DT>(acc[f][2 * p],     af[f], b0);
                    mma_t<DT>(acc[f][2 * p + 1], af[f], b1);
                }
            }
        }
        __syncthreads();                     // buffer (c&1) free for reuse
        if (c + 2 < NC) issue(c + 2);
    }

    // ---- epilogue
    const int gq = lane >> 2, t4 = lane & 3;
    const bool lead = (sk <= 1) || (z == 0);
    #pragma unroll
    for (int f = 0; f < 4; f++) {
        #pragma unroll
        for (int half = 0; half < 2; half++) {
            const int m = bm + wm64 + f * 16 + gq + half * 8;
            const size_t rowo = (size_t)m * ga.N;
            #pragma unroll
            for (int n = 0; n < 4; n++) {
                const int col = bn + wn32 + n * 8 + t4 * 2;
                float vx = acc[f][n][half * 2 + 0];
                float vy = acc[f][n][half * 2 + 1];
                if (ga.bias && lead) {
                    float2 bb = *(const float2*)(ga.bias + col);
                    vx += bb.x; vy += bb.y;
                }
                if (ga.relu) { vx = fmaxf(vx, 0.f); vy = fmaxf(vy, 0.f); }
                if (ga.res && lead) {
                    float2 rr = *(const float2*)(ga.res + rowo + col);
                    vx += rr.x; vy += rr.y;
                }
                if (sk > 1) {
                    atomicAdd(C + rowo + col,     vx);
                    atomicAdd(C + rowo + col + 1, vy);
                } else if (Sh) {
                    *(uint32_t*)(Sh + rowo + col) = pack_t<DT>(vx, vy);
                } else {
                    *(float2*)(C + rowo + col) = make_float2(vx, vy);
                }
            }
        }
    }
}

// ---------------------------------------------------------------- HMMA flash attention (bf16) — R10 config
#define FPITCH 144
#define FQOFF 0
#define FQSZ  (128 * FPITCH)                 // 18432
#define FKOFF FQSZ
#define FSTG  (2 * 64 * FPITCH)              // 18432 (K + V per stage)
#define FMOFF (FKOFF + 2 * FSTG)             // 55296
#define FSMEM (FMOFF + 512)                  // 55808

__global__ void __launch_bounds__(256, 2) flash_mma(
    const __nv_bfloat16* __restrict__ Qb, const __nv_bfloat16* __restrict__ Kb,
    const __nv_bfloat16* __restrict__ Vb, const int* __restrict__ mask,
    __nv_bfloat16* __restrict__ Ohi)
{
    extern __shared__ char fsm[];
    const uint32_t smb = smem_to_u32(fsm);
    const int tid = threadIdx.x, wid = tid >> 5, lane = tid & 31;
    const int gq = lane >> 2, t4 = lane & 3;
    const int bh = blockIdx.x, b = bh / HH, h = bh % HH;
    const int q0 = blockIdx.y * 128;
    const int NIT = SS / 64;

    auto cpKV = [&](int it, int st) {
        const uint32_t ks = smb + FKOFF + st * FSTG;
        const uint32_t vs = ks + 64 * FPITCH;
        const __nv_bfloat16* Ksrc = Kb + (size_t)(b * SS + it * 64) * DD + h * 64;
        const __nv_bfloat16* Vsrc = Vb + (size_t)(b * SS + it * 64) * DD + h * 64;
        #pragma unroll
        for (int i = 0; i < 2; i++) {
            const int idx = tid + i * 256;                 // 0..511
            const int r = idx >> 3, c = idx & 7;
            cp16(ks + r * FPITCH + c * 16, Ksrc + (size_t)r * DD + c * 8);
            cp16(vs + r * FPITCH + c * 16, Vsrc + (size_t)r * DD + c * 8);
        }
        if (tid < 16)
            cp16(smb + FMOFF + st * 256 + tid * 16, mask + b * SS + it * 64 + tid * 4);
        CP_COMMIT();
    };

    {
        const __nv_bfloat16* Qsrc = Qb + (size_t)(b * SS + q0) * DD + h * 64;
        #pragma unroll
        for (int i = 0; i < 4; i++) {
            const int idx = tid + i * 256;                 // 0..1023
            const int r = idx >> 3, c = idx & 7;
            cp16(smb + FQOFF + r * FPITCH + c * 16, Qsrc + (size_t)r * DD + c * 8);
        }
        const uint32_t ks = smb + FKOFF;
        const uint32_t vs = ks + 64 * FPITCH;
        const __nv_bfloat16* Ksrc = Kb + (size_t)(b * SS) * DD + h * 64;
        const __nv_bfloat16* Vsrc = Vb + (size_t)(b * SS) * DD + h * 64;
        #pragma unroll
        for (int i = 0; i < 2; i++) {
            const int idx = tid + i * 256;
            const int r = idx >> 3, c = idx & 7;
            cp16(ks + r * FPITCH + c * 16, Ksrc + (size_t)r * DD + c * 8);
            cp16(vs + r * FPITCH + c * 16, Vsrc + (size_t)r * DD + c * 8);
        }
        if (tid < 16)
            cp16(smb + FMOFF + tid * 16, mask + b * SS + tid * 4);
        CP_COMMIT();
        cpKV(1, 1);
    }

    CP_WAIT1();
    __syncthreads();

    uint32_t aq[4][4];
    #pragma unroll
    for (int kc = 0; kc < 4; kc++) {
        uint32_t addr = smb + FQOFF
                      + (uint32_t)((wid * 16 + (lane & 15)) * FPITCH
                                   + (kc * 16 + ((lane >> 4) << 3)) * 2);
        ldsm_x4(aq[kc], addr);
    }

    float oacc[8][4];
    #pragma unroll
    for (int n = 0; n < 8; n++)
        #pragma unroll
        for (int e = 0; e < 4; e++) oacc[n][e] = 0.f;
    float l0 = 0.f, l1 = 0.f;

    for (int it = 0; it < NIT; it++) {
        if (it > 0) {
            if (it + 1 < NIT) { CP_WAIT1(); } else { CP_WAIT0(); }
            __syncthreads();
        }
        const int st = it & 1;
        const uint32_t ks = smb + FKOFF + st * FSTG;
        const uint32_t vs = ks + 64 * FPITCH;
        const int* Mi = (const int*)(fsm + FMOFF + st * 256);

        float sacc[8][4];
        #pragma unroll
        for (int j = 0; j < 8; j++)
            #pragma unroll
            for (int e = 0; e < 4; e++) sacc[j][e] = 0.f;

        #pragma unroll
        for (int kc = 0; kc < 4; kc++) {
            uint32_t bfr[4][4];
            #pragma unroll
            for (int jj = 0; jj < 4; jj++) {
                uint32_t addr = ks + (uint32_t)((jj * 16 + ((lane >> 4) << 3) + (lane & 7)) * FPITCH
                                                + (kc * 16 + (((lane >> 3) & 1) << 3)) * 2);
                ldsm_x4(bfr[jj], addr);
            }
            #pragma unroll
            for (int jj = 0; jj < 4; jj++) {
                uint32_t b0[2] = { bfr[jj][0], bfr[jj][1] };
                uint32_t b1[2] = { bfr[jj][2], bfr[jj][3] };
                mma_bf16(sacc[2 * jj],     aq[kc], b0);
                mma_bf16(sacc[2 * jj + 1], aq[kc], b1);
            }
        }

        uint32_t pf[8][2];
        #pragma unroll
        for (int j = 0; j < 8; j++) {
            const int col = j * 8 + t4 * 2;
            const int m0 = Mi[col], m1 = Mi[col + 1];
            float s0 = m0 ? sacc[j][0] * 0.125f : 1e-9f;
            float s1 = m1 ? sacc[j][1] * 0.125f : 1e-9f;
            float s2 = m0 ? sacc[j][2] * 0.125f : 1e-9f;
            float s3 = m1 ? sacc[j][3] * 0.125f : 1e-9f;
            float p0 = __expf(s0), p1 = __expf(s1), p2 = __expf(s2), p3 = __expf(s3);
            l0 += p0 + p1;
            l1 += p2 + p3;
            pf[j][0] = cvt_bf2(p0, p1);
            pf[j][1] = cvt_bf2(p2, p3);
        }

        #pragma unroll
        for (int jk = 0; jk < 4; jk++) {
            uint32_t a[4] = { pf[2 * jk][0], pf[2 * jk][1], pf[2 * jk + 1][0], pf[2 * jk + 1][1] };
            #pragma unroll
            for (int nn = 0; nn < 4; nn++) {
                uint32_t bv[4];
                uint32_t addr = vs + (uint32_t)((jk * 16 + (((lane >> 3) & 1) << 3) + (lane & 7)) * FPITCH
                                                + (nn * 16 + ((lane >> 4) << 3)) * 2);
                ldsm_x4_t(bv, addr);
                uint32_t b0[2] = { bv[0], bv[1] };
                uint32_t b1[2] = { bv[2], bv[3] };
                mma_bf16(oacc[2 * nn],     a, b0);
                mma_bf16(oacc[2 * nn + 1], a, b1);
            }
        }

        __syncthreads();
        if (it + 2 < NIT) cpKV(it + 2, st);
    }

    l0 += __shfl_xor_sync(0xffffffffu, l0, 1);
    l0 += __shfl_xor_sync(0xffffffffu, l0, 2);
    l1 += __shfl_xor_sync(0xffffffffu, l1, 1);
    l1 += __shfl_xor_sync(0xffffffffu, l1, 2);
    const float inv0 = 1.f / l0, inv1 = 1.f / l1;

    const int r0 = b * SS + q0 + wid * 16 + gq;
    const int r1 = r0 + 8;
    #pragma unroll
    for (int nn = 0; nn < 8; nn++) {
        const int col = h * 64 + nn * 8 + t4 * 2;
        *(uint32_t*)(Ohi + (size_t)r0 * DD + col) =
            cvt_bf2(oacc[nn][0] * inv0, oacc[nn][1] * inv0);
        *(uint32_t*)(Ohi + (size_t)r1 * DD + col) =
            cvt_bf2(oacc[nn][2] * inv1, oacc[nn][3] * inv1);
    }
}

// ---------------------------------------------------------------- launch
extern "C" void kernel_launch(void* const* d_in, const int* in_sizes, int n_in,
                              void* d_out, int out_size)
{
    const float* x    = (const float*)d_in[0];
    const int*   mask = (const int*)  d_in[1];
    const float* wq   = (const float*)d_in[2];
    const float* wk   = (const float*)d_in[3];
    const float* wv   = (const float*)d_in[4];
    const float* wo   = (const float*)d_in[5];
    const float* w1   = (const float*)d_in[6];
    const float* b1   = (const float*)d_in[7];
    const float* w2   = (const float*)d_in[8];
    const float* b2   = (const float*)d_in[9];
    const float* ln1a = (const float*)d_in[10];
    const float* ln1b = (const float*)d_in[11];
    const float* ln2a = (const float*)d_in[12];
    const float* ln2b = (const float*)d_in[13];
    float* out = (float*)d_out;

    __nv_bfloat16 *thi, *chi, *qb, *kb, *vb;
    __nv_bfloat16 *wqhi, *wkhi, *wvhi, *wohi;
    __half *t16, *h1, *w1h, *w2h;
    float *x2;
    cudaGetSymbolAddress((void**)&thi, g_thi);
    cudaGetSymbolAddress((void**)&t16, g_t16);
    cudaGetSymbolAddress((void**)&chi, g_chi);
    cudaGetSymbolAddress((void**)&h1, g_h1);
    cudaGetSymbolAddress((void**)&qb, g_qb);     cudaGetSymbolAddress((void**)&kb, g_kb);
    cudaGetSymbolAddress((void**)&vb, g_vb);
    cudaGetSymbolAddress((void**)&wqhi, g_wqhi);
    cudaGetSymbolAddress((void**)&wkhi, g_wkhi);
    cudaGetSymbolAddress((void**)&wvhi, g_wvhi);
    cudaGetSymbolAddress((void**)&wohi, g_wohi);
    cudaGetSymbolAddress((void**)&w1h, g_w1h);
    cudaGetSymbolAddress((void**)&w2h, g_w2h);
    cudaGetSymbolAddress((void**)&x2, g_x2);

    cudaFuncSetAttribute(mma_gemm<0>, cudaFuncAttributeMaxDynamicSharedMemorySize, GSMEM);
    cudaFuncSetAttribute(mma_gemm<1>, cudaFuncAttributeMaxDynamicSharedMemorySize, GSMEM);
    cudaFuncSetAttribute(flash_mma, cudaFuncAttributeMaxDynamicSharedMemorySize, FSMEM);

    // fused weight transpose (bf16 for q/k/v/o; fp16 for w1/w2)
    WSArgs wa = {};
    wa.W[0] = wq; wa.Hi[0] = wqhi; wa.dt[0] = 0; wa.Kd[0] = DD; wa.Nd[0] = DD;
    wa.W[1] = wk; wa.Hi[1] = wkhi; wa.dt[1] = 0; wa.Kd[1] = DD; wa.Nd[1] = DD;
    wa.W[2] = wv; wa.Hi[2] = wvhi; wa.dt[2] = 0; wa.Kd[2] = DD; wa.Nd[2] = DD;
    wa.W[3] = wo; wa.Hi[3] = wohi; wa.dt[3] = 0; wa.Kd[3] = DD; wa.Nd[3] = DD;
    wa.W[4] = w1; wa.Hi[4] = w1h;  wa.dt[4] = 1; wa.Kd[4] = DD; wa.Nd[4] = FF;
    wa.W[5] = w2; wa.Hi[5] = w2h;  wa.dt[5] = 1; wa.Kd[5] = FF; wa.Nd[5] = DD;
    int acc0 = 0;
    wa.start[0] = 0;
    for (int e = 0; e < 6; e++) {
        acc0 += (wa.Nd[e] / 32) * (wa.Kd[e] / 32);
        wa.start[e + 1] = acc0;
    }
    ws_all<<<acc0, dim3(32, 8)>>>(wa);

    // LN1 -> bf16
    ln_kernel<0><<<NROW, 256>>>(x, thi, ln1a, ln1b);

    // Q/K/V projections (bf16, z-batched)
    GemmArgs aq = {};
    aq.A = thi;
    aq.B0 = wqhi; aq.B1 = wkhi; aq.B2 = wvhi;
    aq.S0 = qb; aq.S1 = kb; aq.S2 = vb;
    aq.N = DD; aq.K = DD; aq.splitk = 1;
    mma_gemm<0><<<dim3(DD / 128, NROW / 128, 3), 256, GSMEM>>>(aq);

    // attention -> bf16 context (128 queries / CTA)
    flash_mma<<<dim3(BB * HH, SS / 128), 256, FSMEM>>>(qb, kb, vb, mask, chi);

    // x2 = x + ctx @ wo (bf16, split-K=3, atomic accumulate)
    cudaMemsetAsync(x2, 0, (size_t)NROW * DD * sizeof(float));
    GemmArgs ao = {};
    ao.A = chi;
    ao.B0 = wohi;
    ao.C0 = x2;
    ao.res = x;
    ao.N = DD; ao.K = DD; ao.splitk = 3;
    mma_gemm<0><<<dim3(DD / 128, NROW / 128, 3), 256, GSMEM>>>(ao);

    // LN2 -> fp16
    ln_kernel<1><<<NROW, 256>>>(x2, t16, ln2a, ln2b);

    // FFN1: h1 = relu(t @ w1 + b1) (fp16)
    GemmArgs a1 = {};
    a1.A = t16;
    a1.B0 = w1h;
    a1.bias = b1; a1.relu = 1;
    a1.S0 = h1;
    a1.N = FF; a1.K = DD; a1.splitk = 1;
    mma_gemm<1><<<dim3(FF / 128, NROW / 128, 1), 256, GSMEM>>>(a1);

    // FFN2: out = x2 + h1 @ w2 + b2 (fp16, split-K=3, atomic accumulate)
    cudaMemsetAsync(out, 0, (size_t)NROW * DD * sizeof(float));
    GemmArgs a2 = {};
    a2.A = h1;
    a2.B0 = w2h;
    a2.C0 = out;
    a2.bias = b2; a2.res = x2;
    a2.N = DD; a2.K = FF; a2.splitk = 3;
    mma_gemm<1><<<dim3(DD / 128, NROW / 128, 3), 256, GSMEM>>>(a2);
}

// round 13
// speedup vs baseline: 1.2329x; 1.0357x over previous
#include <cuda_runtime.h>
#include <cuda_bf16.h>
#include <cuda_fp16.h>
#include <cstdint>
#include <math.h>

#define BB 2
#define SS 2048
#define DD 768
#define FF 3072
#define HH 12
#define DKK 64
#define NROW (BB*SS)   // 4096

// ---------------------------------------------------------------- scratch
__device__ __nv_bfloat16 g_thi[NROW*DD];
__device__ __half        g_t16[NROW*DD];
__device__ __nv_bfloat16 g_qb[NROW*DD], g_kb[NROW*DD], g_vb[NROW*DD];
__device__ float g_x2[NROW*DD];
__device__ __nv_bfloat16 g_chi[NROW*DD];
__device__ __half        g_h1[NROW*FF];
__device__ __nv_bfloat16 g_wqhi[DD*DD];
__device__ __nv_bfloat16 g_wkhi[DD*DD];
__device__ __nv_bfloat16 g_wvhi[DD*DD];
__device__ __nv_bfloat16 g_wohi[DD*DD];
__device__ __half        g_w1h[FF*DD];   // [F,D] = w1^T (fp16)
__device__ __half        g_w2h[DD*FF];   // [D,F] = w2^T (fp16)

// ---------------------------------------------------------------- helpers
__device__ __forceinline__ uint32_t smem_to_u32(const void* p) {
    uint32_t a;
    asm("{ .reg .u64 t; cvta.to.shared.u64 t, %1; cvt.u32.u64 %0, t; }" : "=r"(a) : "l"(p));
    return a;
}
__device__ __forceinline__ void ldsm_x4(uint32_t (&r)[4], uint32_t addr) {
    asm volatile("ldmatrix.sync.aligned.m8n8.x4.shared.b16 {%0,%1,%2,%3}, [%4];"
                 : "=r"(r[0]), "=r"(r[1]), "=r"(r[2]), "=r"(r[3]) : "r"(addr));
}
__device__ __forceinline__ void ldsm_x4_t(uint32_t (&r)[4], uint32_t addr) {
    asm volatile("ldmatrix.sync.aligned.m8n8.x4.trans.shared.b16 {%0,%1,%2,%3}, [%4];"
                 : "=r"(r[0]), "=r"(r[1]), "=r"(r[2]), "=r"(r[3]) : "r"(addr));
}
__device__ __forceinline__ void mma_bf16(float (&c)[4], const uint32_t (&a)[4], const uint32_t (&b)[2]) {
    asm volatile("mma.sync.aligned.m16n8k16.row.col.f32.bf16.bf16.f32 "
                 "{%0,%1,%2,%3}, {%4,%5,%6,%7}, {%8,%9}, {%0,%1,%2,%3};"
                 : "+f"(c[0]), "+f"(c[1]), "+f"(c[2]), "+f"(c[3])
                 : "r"(a[0]), "r"(a[1]), "r"(a[2]), "r"(a[3]), "r"(b[0]), "r"(b[1]));
}
__device__ __forceinline__ void mma_f16(float (&c)[4], const uint32_t (&a)[4], const uint32_t (&b)[2]) {
    asm volatile("mma.sync.aligned.m16n8k16.row.col.f32.f16.f16.f32 "
                 "{%0,%1,%2,%3}, {%4,%5,%6,%7}, {%8,%9}, {%0,%1,%2,%3};"
                 : "+f"(c[0]), "+f"(c[1]), "+f"(c[2]), "+f"(c[3])
                 : "r"(a[0]), "r"(a[1]), "r"(a[2]), "r"(a[3]), "r"(b[0]), "r"(b[1]));
}
__device__ __forceinline__ void cp16(uint32_t dst, const void* src) {
    asm volatile("cp.async.cg.shared.global [%0], [%1], 16;" :: "r"(dst), "l"(src));
}
#define CP_COMMIT() asm volatile("cp.async.commit_group;" ::: "memory")
#define CP_WAIT1()  asm volatile("cp.async.wait_group 1;" ::: "memory")
#define CP_WAIT0()  asm volatile("cp.async.wait_group 0;" ::: "memory")

__device__ __forceinline__ uint32_t cvt_bf2(float lo, float hi) {
    uint32_t r;
    asm("cvt.rn.bf16x2.f32 %0, %1, %2;" : "=r"(r) : "f"(hi), "f"(lo));
    return r;
}

template<int DT> struct Elem    { using T = __nv_bfloat16; };
template<>       struct Elem<1> { using T = __half; };

template<int DT>
__device__ __forceinline__ void mma_t(float (&c)[4], const uint32_t (&a)[4], const uint32_t (&b)[2]) {
    if constexpr (DT == 0) mma_bf16(c, a, b); else mma_f16(c, a, b);
}
template<int DT>
__device__ __forceinline__ uint32_t pack_t(float x, float y) {
    if constexpr (DT == 0) {
        return cvt_bf2(x, y);
    } else {
        __half2 h = __floats2half2_rn(x, y);
        return *(uint32_t*)&h;
    }
}

// ---------------------------------------------------------------- LayerNorm -> T (single pass; optional row-zeroing of zbuf)
template<int DT>
__global__ void ln_kernel(const float* __restrict__ x,
                          typename Elem<DT>::T* __restrict__ hi,
                          const float* __restrict__ alpha_p, const float* __restrict__ bias_p,
                          float* __restrict__ zbuf)
{
    const int row = blockIdx.x;
    const float* xr = x + (size_t)row * DD;
    const int tid = threadIdx.x, lane = tid & 31, wid = tid >> 5;
    __shared__ float red[8], red2[8];
    __shared__ float s_mean, s_scale;

    // zero the split-K destination row (replaces cudaMemsetAsync)
    if (zbuf) {
        float* zr = zbuf + (size_t)row * DD;
        for (int i = tid; i < DD; i += 256) zr[i] = 0.f;
    }

    float s = 0.f, s2 = 0.f;
    float v0 = 0.f, v1 = 0.f, v2 = 0.f;
    {
        // DD = 768 = 3 * 256: each thread reads exactly 3 elements
        v0 = xr[tid];
        v1 = xr[tid + 256];
        v2 = xr[tid + 512];
        s  = v0 + v1 + v2;
        s2 = v0 * v0 + v1 * v1 + v2 * v2;
    }
    #pragma unroll
    for (int o = 16; o; o >>= 1) {
        s  += __shfl_xor_sync(0xffffffffu, s, o);
        s2 += __shfl_xor_sync(0xffffffffu, s2, o);
    }
    if (lane == 0) { red[wid] = s; red2[wid] = s2; }
    __syncthreads();
    if (tid == 0) {
        float t = 0.f, t2 = 0.f;
        #pragma unroll
        for (int i = 0; i < 8; i++) { t += red[i]; t2 += red2[i]; }
        const float mean = t / (float)DD;
        const float var = (t2 - (float)DD * mean * mean) / (float)(DD - 1);
        s_mean = mean;
        s_scale = alpha_p[0] / (sqrtf(fmaxf(var, 0.f)) + 1e-6f);
    }
    __syncthreads();
    const float mean = s_mean, scale = s_scale, bias = bias_p[0];

    {
        float y0 = (v0 - mean) * scale + bias;
        float y1 = (v1 - mean) * scale + bias;
        float y2 = (v2 - mean) * scale + bias;
        if constexpr (DT == 0) {
            hi[(size_t)row * DD + tid]       = __float2bfloat16(y0);
            hi[(size_t)row * DD + tid + 256] = __float2bfloat16(y1);
            hi[(size_t)row * DD + tid + 512] = __float2bfloat16(y2);
        } else {
            hi[(size_t)row * DD + tid]       = __float2half(y0);
            hi[(size_t)row * DD + tid + 256] = __float2half(y1);
            hi[(size_t)row * DD + tid + 512] = __float2half(y2);
        }
    }
}

// ---------------------------------------------------------------- fused weight transpose (mixed dtype)
struct WSArgs {
    const float* W[6];
    void* Hi[6];
    int dt[6];
    int Kd[6], Nd[6];
    int start[7];
};

__global__ void ws_all(WSArgs a)
{
    __shared__ float t[32][33];
    int bidx = blockIdx.x;
    int e = 0;
    while (bidx >= a.start[e + 1]) e++;
    const int rel = bidx - a.start[e];
    const int Kd = a.Kd[e], Nd = a.Nd[e];
    const int nx = Nd / 32;
    const int n0 = (rel % nx) * 32, k0 = (rel / nx) * 32;
    const float* W = a.W[e];
    void* Hi = a.Hi[e];
    const int dt = a.dt[e];

    const int tx = threadIdx.x, ty = threadIdx.y;   // 32x8
    #pragma unroll
    for (int r = 0; r < 4; r++)
        t[ty + 8 * r][tx] = W[(size_t)(k0 + ty + 8 * r) * Nd + n0 + tx];
    __syncthreads();
    #pragma unroll
    for (int r = 0; r < 4; r++) {
        float v = t[tx][ty + 8 * r];
        size_t o = (size_t)(n0 + ty + 8 * r) * Kd + k0 + tx;
        if (dt == 0) ((__nv_bfloat16*)Hi)[o] = __float2bfloat16(v);
        else         ((__half*)Hi)[o]        = __float2half(v);
    }
}

// ---------------------------------------------------------------- HMMA GEMM: 8 warps, warp tile 64x32, 2-stage K64
// C = A @ B^T, B given [N,K]; DT: 0=bf16, 1=fp16. 16 warps/SM via 2 CTAs.
// splitk > 1: blockIdx.z indexes a K-partition; partials atomicAdd into
// zero-initialized C; partition 0 carries bias (+res).
struct GemmArgs {
    const void *A;
    const void *B0, *B1, *B2;
    float *C0, *C1, *C2;
    const float *bias, *res;
    void *S0, *S1, *S2;          // optional T outputs (not valid with splitk)
    int relu, N, K, splitk;
};

#define GP 144                        // row pitch bytes for 64-elem (128B) rows
#define GTILE (128 * GP)              // 18432
#define GSTG  (2 * GTILE)             // 36864 (A + B)
#define GSMEM (2 * GSTG)              // 73728 (2 stages)

template<int DT>
__global__ void __launch_bounds__(256, 2) mma_gemm(GemmArgs ga)
{
    using T = typename Elem<DT>::T;
    extern __shared__ char smc[];
    const uint32_t smb = smem_to_u32(smc);
    const int tid = threadIdx.x, wid = tid >> 5, lane = tid & 31;
    const int bn = blockIdx.x * 128, bm = blockIdx.y * 128;
    const int z = blockIdx.z;
    const int sk = ga.splitk;
    const T* A = (const T*)ga.A;
    const T* B; float* C; T* Sh;
    int c0, NC;
    if (sk > 1) {
        B = (const T*)ga.B0; C = ga.C0; Sh = nullptr;
        NC = ga.K / 64 / sk;
        c0 = z * NC;
    } else {
        B = (const T*)((z == 0) ? ga.B0 : ((z == 1) ? ga.B1 : ga.B2));
        C = (z == 0) ? ga.C0 : ((z == 1) ? ga.C1 : ga.C2);
        Sh = (T*)((z == 0) ? ga.S0 : ((z == 1) ? ga.S1 : ga.S2));
        NC = ga.K / 64;
        c0 = 0;
    }
    const int K = ga.K;

    const int wm64 = (wid & 1) * 64;       // 2 warps over M
    const int wn32 = (wid >> 1) * 32;      // 4 warps over N

    float acc[4][4][4];
    #pragma unroll
    for (int f = 0; f < 4; f++)
        #pragma unroll
        for (int n = 0; n < 4; n++)
            #pragma unroll
            for (int e = 0; e < 4; e++) acc[f][n][e] = 0.f;

    auto issue = [&](int c) {
        const int ks = (c0 + c) * 64;
        const uint32_t base = smb + (uint32_t)(c & 1) * GSTG;
        #pragma unroll
        for (int i = 0; i < 8; i++) {
            const int u = tid + i * 256;                 // 0..2047
            const int row = (u >> 3) & 127, c16 = u & 7;
            const uint32_t dst = base + ((u < 1024) ? 0u : (uint32_t)GTILE)
                               + row * GP + c16 * 16;
            const T* src = (u < 1024)
                ? (A + (size_t)(bm + row) * K + ks + c16 * 8)
                : (B + (size_t)(bn + row) * K + ks + c16 * 8);
            cp16(dst, src);
        }
        CP_COMMIT();
    };

    issue(0);
    if (NC > 1) issue(1);

    const uint32_t aBase0 = smb + (uint32_t)((wm64 + (lane & 15)) * GP + ((lane >> 4) << 3) * 2);
    const uint32_t bBase0 = smb + (uint32_t)GTILE
                          + (uint32_t)((wn32 + ((lane >> 4) << 3) + (lane & 7)) * GP
                                       + (((lane >> 3) & 1) << 3) * 2);

    for (int c = 0; c < NC; c++) {
        if (c + 1 < NC) { CP_WAIT1(); } else { CP_WAIT0(); }
        __syncthreads();

        const uint32_t stg = (uint32_t)(c & 1) * GSTG;
        uint32_t aAddr = aBase0 + stg;
        uint32_t bAddr = bBase0 + stg;
        #pragma unroll
        for (int kk = 0; kk < 4; kk++) {
            uint32_t af[4][4];
            #pragma unroll
            for (int f = 0; f < 4; f++)
                ldsm_x4(af[f], aAddr + (uint32_t)(f * 16 * GP));
            uint32_t bq[2][4];
            #pragma unroll
            for (int p = 0; p < 2; p++)
                ldsm_x4(bq[p], bAddr + (uint32_t)(p * 16 * GP));
            aAddr += 32;
            bAddr += 32;
            #pragma unroll
            for (int f = 0; f < 4; f++) {
                #pragma unroll
                for (int p = 0; p < 2; p++) {
                    uint32_t b0[2] = { bq[p][0], bq[p][1] };
                    uint32_t b1[2] = { bq[p][2], bq[p][3] };
                    mma_t<DT>(acc[f][2 * p],     af[f], b0);
                    mma_t<DT>(acc[f][2 * p + 1], af[f], b1);
                }
            }
        }
        __syncthreads();                     // buffer (c&1) free for reuse
        if (c + 2 < NC) issue(c + 2);
    }

    // ---- epilogue
    const int gq = lane >> 2, t4 = lane & 3;
    const bool lead = (sk <= 1) || (z == 0);
    #pragma unroll
    for (int f = 0; f < 4; f++) {
        #pragma unroll
        for (int half = 0; half < 2; half++) {
            const int m = bm + wm64 + f * 16 + gq + half * 8;
            const size_t rowo = (size_t)m * ga.N;
            #pragma unroll
            for (int n = 0; n < 4; n++) {
                const int col = bn + wn32 + n * 8 + t4 * 2;
                float vx = acc[f][n][half * 2 + 0];
                float vy = acc[f][n][half * 2 + 1];
                if (ga.bias && lead) {
                    float2 bb = *(const float2*)(ga.bias + col);
                    vx += bb.x; vy += bb.y;
                }
                if (ga.relu) { vx = fmaxf(vx, 0.f); vy = fmaxf(vy, 0.f); }
                if (ga.res && lead) {
                    float2 rr = *(const float2*)(ga.res + rowo + col);
                    vx += rr.x; vy += rr.y;
                }
                if (sk > 1) {
                    atomicAdd(C + rowo + col,     vx);
                    atomicAdd(C + rowo + col + 1, vy);
                } else if (Sh) {
                    *(uint32_t*)(Sh + rowo + col) = pack_t<DT>(vx, vy);
                } else {
                    *(float2*)(C + rowo + col) = make_float2(vx, vy);
                }
            }
        }
    }
}

// ---------------------------------------------------------------- HMMA flash attention (bf16) — R10 config
#define FPITCH 144
#define FQOFF 0
#define FQSZ  (128 * FPITCH)                 // 18432
#define FKOFF FQSZ
#define FSTG  (2 * 64 * FPITCH)              // 18432 (K + V per stage)
#define FMOFF (FKOFF + 2 * FSTG)             // 55296
#define FSMEM (FMOFF + 512)                  // 55808

__global__ void __launch_bounds__(256, 2) flash_mma(
    const __nv_bfloat16* __restrict__ Qb, const __nv_bfloat16* __restrict__ Kb,
    const __nv_bfloat16* __restrict__ Vb, const int* __restrict__ mask,
    __nv_bfloat16* __restrict__ Ohi)
{
    extern __shared__ char fsm[];
    const uint32_t smb = smem_to_u32(fsm);
    const int tid = threadIdx.x, wid = tid >> 5, lane = tid & 31;
    const int gq = lane >> 2, t4 = lane & 3;
    const int bh = blockIdx.x, b = bh / HH, h = bh % HH;
    const int q0 = blockIdx.y * 128;
    const int NIT = SS / 64;

    auto cpKV = [&](int it, int st) {
        const uint32_t ks = smb + FKOFF + st * FSTG;
        const uint32_t vs = ks + 64 * FPITCH;
        const __nv_bfloat16* Ksrc = Kb + (size_t)(b * SS + it * 64) * DD + h * 64;
        const __nv_bfloat16* Vsrc = Vb + (size_t)(b * SS + it * 64) * DD + h * 64;
        #pragma unroll
        for (int i = 0; i < 2; i++) {
            const int idx = tid + i * 256;                 // 0..511
            const int r = idx >> 3, c = idx & 7;
            cp16(ks + r * FPITCH + c * 16, Ksrc + (size_t)r * DD + c * 8);
            cp16(vs + r * FPITCH + c * 16, Vsrc + (size_t)r * DD + c * 8);
        }
        if (tid < 16)
            cp16(smb + FMOFF + st * 256 + tid * 16, mask + b * SS + it * 64 + tid * 4);
        CP_COMMIT();
    };

    {
        const __nv_bfloat16* Qsrc = Qb + (size_t)(b * SS + q0) * DD + h * 64;
        #pragma unroll
        for (int i = 0; i < 4; i++) {
            const int idx = tid + i * 256;                 // 0..1023
            const int r = idx >> 3, c = idx & 7;
            cp16(smb + FQOFF + r * FPITCH + c * 16, Qsrc + (size_t)r * DD + c * 8);
        }
        const uint32_t ks = smb + FKOFF;
        const uint32_t vs = ks + 64 * FPITCH;
        const __nv_bfloat16* Ksrc = Kb + (size_t)(b * SS) * DD + h * 64;
        const __nv_bfloat16* Vsrc = Vb + (size_t)(b * SS) * DD + h * 64;
        #pragma unroll
        for (int i = 0; i < 2; i++) {
            const int idx = tid + i * 256;
            const int r = idx >> 3, c = idx & 7;
            cp16(ks + r * FPITCH + c * 16, Ksrc + (size_t)r * DD + c * 8);
            cp16(vs + r * FPITCH + c * 16, Vsrc + (size_t)r * DD + c * 8);
        }
        if (tid < 16)
            cp16(smb + FMOFF + tid * 16, mask + b * SS + tid * 4);
        CP_COMMIT();
        cpKV(1, 1);
    }

    CP_WAIT1();
    __syncthreads();

    uint32_t aq[4][4];
    #pragma unroll
    for (int kc = 0; kc < 4; kc++) {
        uint32_t addr = smb + FQOFF
                      + (uint32_t)((wid * 16 + (lane & 15)) * FPITCH
                                   + (kc * 16 + ((lane >> 4) << 3)) * 2);
        ldsm_x4(aq[kc], addr);
    }

    float oacc[8][4];
    #pragma unroll
    for (int n = 0; n < 8; n++)
        #pragma unroll
        for (int e = 0; e < 4; e++) oacc[n][e] = 0.f;
    float l0 = 0.f, l1 = 0.f;

    for (int it = 0; it < NIT; it++) {
        if (it > 0) {
            if (it + 1 < NIT) { CP_WAIT1(); } else { CP_WAIT0(); }
            __syncthreads();
        }
        const int st = it & 1;
        const uint32_t ks = smb + FKOFF + st * FSTG;
        const uint32_t vs = ks + 64 * FPITCH;
        const int* Mi = (const int*)(fsm + FMOFF + st * 256);

        float sacc[8][4];
        #pragma unroll
        for (int j = 0; j < 8; j++)
            #pragma unroll
            for (int e = 0; e < 4; e++) sacc[j][e] = 0.f;

        #pragma unroll
        for (int kc = 0; kc < 4; kc++) {
            uint32_t bfr[4][4];
            #pragma unroll
            for (int jj = 0; jj < 4; jj++) {
                uint32_t addr = ks + (uint32_t)((jj * 16 + ((lane >> 4) << 3) + (lane & 7)) * FPITCH
                                                + (kc * 16 + (((lane >> 3) & 1) << 3)) * 2);
                ldsm_x4(bfr[jj], addr);
            }
            #pragma unroll
            for (int jj = 0; jj < 4; jj++) {
                uint32_t b0[2] = { bfr[jj][0], bfr[jj][1] };
                uint32_t b1[2] = { bfr[jj][2], bfr[jj][3] };
                mma_bf16(sacc[2 * jj],     aq[kc], b0);
                mma_bf16(sacc[2 * jj + 1], aq[kc], b1);
            }
        }

        uint32_t pf[8][2];
        #pragma unroll
        for (int j = 0; j < 8; j++) {
            const int col = j * 8 + t4 * 2;
            const int m0 = Mi[col], m1 = Mi[col + 1];
            float s0 = m0 ? sacc[j][0] * 0.125f : 1e-9f;
            float s1 = m1 ? sacc[j][1] * 0.125f : 1e-9f;
            float s2 = m0 ? sacc[j][2] * 0.125f : 1e-9f;
            float s3 = m1 ? sacc[j][3] * 0.125f : 1e-9f;
            float p0 = __expf(s0), p1 = __expf(s1), p2 = __expf(s2), p3 = __expf(s3);
            l0 += p0 + p1;
            l1 += p2 + p3;
            pf[j][0] = cvt_bf2(p0, p1);
            pf[j][1] = cvt_bf2(p2, p3);
        }

        #pragma unroll
        for (int jk = 0; jk < 4; jk++) {
            uint32_t a[4] = { pf[2 * jk][0], pf[2 * jk][1], pf[2 * jk + 1][0], pf[2 * jk + 1][1] };
            #pragma unroll
            for (int nn = 0; nn < 4; nn++) {
                uint32_t bv[4];
                uint32_t addr = vs + (uint32_t)((jk * 16 + (((lane >> 3) & 1) << 3) + (lane & 7)) * FPITCH
                                                + (nn * 16 + ((lane >> 4) << 3)) * 2);
                ldsm_x4_t(bv, addr);
                uint32_t b0[2] = { bv[0], bv[1] };
                uint32_t b1[2] = { bv[2], bv[3] };
                mma_bf16(oacc[2 * nn],     a, b0);
                mma_bf16(oacc[2 * nn + 1], a, b1);
            }
        }

        __syncthreads();
        if (it + 2 < NIT) cpKV(it + 2, st);
    }

    l0 += __shfl_xor_sync(0xffffffffu, l0, 1);
    l0 += __shfl_xor_sync(0xffffffffu, l0, 2);
    l1 += __shfl_xor_sync(0xffffffffu, l1, 1);
    l1 += __shfl_xor_sync(0xffffffffu, l1, 2);
    const float inv0 = 1.f / l0, inv1 = 1.f / l1;

    const int r0 = b * SS + q0 + wid * 16 + gq;
    const int r1 = r0 + 8;
    #pragma unroll
    for (int nn = 0; nn < 8; nn++) {
        const int col = h * 64 + nn * 8 + t4 * 2;
        *(uint32_t*)(Ohi + (size_t)r0 * DD + col) =
            cvt_bf2(oacc[nn][0] * inv0, oacc[nn][1] * inv0);
        *(uint32_t*)(Ohi + (size_t)r1 * DD + col) =
            cvt_bf2(oacc[nn][2] * inv1, oacc[nn][3] * inv1);
    }
}

// ---------------------------------------------------------------- launch
extern "C" void kernel_launch(void* const* d_in, const int* in_sizes, int n_in,
                              void* d_out, int out_size)
{
    const float* x    = (const float*)d_in[0];
    const int*   mask = (const int*)  d_in[1];
    const float* wq   = (const float*)d_in[2];
    const float* wk   = (const float*)d_in[3];
    const float* wv   = (const float*)d_in[4];
    const float* wo   = (const float*)d_in[5];
    const float* w1   = (const float*)d_in[6];
    const float* b1   = (const float*)d_in[7];
    const float* w2   = (const float*)d_in[8];
    const float* b2   = (const float*)d_in[9];
    const float* ln1a = (const float*)d_in[10];
    const float* ln1b = (const float*)d_in[11];
    const float* ln2a = (const float*)d_in[12];
    const float* ln2b = (const float*)d_in[13];
    float* out = (float*)d_out;

    __nv_bfloat16 *thi, *chi, *qb, *kb, *vb;
    __nv_bfloat16 *wqhi, *wkhi, *wvhi, *wohi;
    __half *t16, *h1, *w1h, *w2h;
    float *x2;
    cudaGetSymbolAddress((void**)&thi, g_thi);
    cudaGetSymbolAddress((void**)&t16, g_t16);
    cudaGetSymbolAddress((void**)&chi, g_chi);
    cudaGetSymbolAddress((void**)&h1, g_h1);
    cudaGetSymbolAddress((void**)&qb, g_qb);     cudaGetSymbolAddress((void**)&kb, g_kb);
    cudaGetSymbolAddress((void**)&vb, g_vb);
    cudaGetSymbolAddress((void**)&wqhi, g_wqhi);
    cudaGetSymbolAddress((void**)&wkhi, g_wkhi);
    cudaGetSymbolAddress((void**)&wvhi, g_wvhi);
    cudaGetSymbolAddress((void**)&wohi, g_wohi);
    cudaGetSymbolAddress((void**)&w1h, g_w1h);
    cudaGetSymbolAddress((void**)&w2h, g_w2h);
    cudaGetSymbolAddress((void**)&x2, g_x2);

    cudaFuncSetAttribute(mma_gemm<0>, cudaFuncAttributeMaxDynamicSharedMemorySize, GSMEM);
    cudaFuncSetAttribute(mma_gemm<1>, cudaFuncAttributeMaxDynamicSharedMemorySize, GSMEM);
    cudaFuncSetAttribute(flash_mma, cudaFuncAttributeMaxDynamicSharedMemorySize, FSMEM);

    // fused weight transpose (bf16 for q/k/v/o; fp16 for w1/w2)
    WSArgs wa = {};
    wa.W[0] = wq; wa.Hi[0] = wqhi; wa.dt[0] = 0; wa.Kd[0] = DD; wa.Nd[0] = DD;
    wa.W[1] = wk; wa.Hi[1] = wkhi; wa.dt[1] = 0; wa.Kd[1] = DD; wa.Nd[1] = DD;
    wa.W[2] = wv; wa.Hi[2] = wvhi; wa.dt[2] = 0; wa.Kd[2] = DD; wa.Nd[2] = DD;
    wa.W[3] = wo; wa.Hi[3] = wohi; wa.dt[3] = 0; wa.Kd[3] = DD; wa.Nd[3] = DD;
    wa.W[4] = w1; wa.Hi[4] = w1h;  wa.dt[4] = 1; wa.Kd[4] = DD; wa.Nd[4] = FF;
    wa.W[5] = w2; wa.Hi[5] = w2h;  wa.dt[5] = 1; wa.Kd[5] = FF; wa.Nd[5] = DD;
    int acc0 = 0;
    wa.start[0] = 0;
    for (int e = 0; e < 6; e++) {
        acc0 += (wa.Nd[e] / 32) * (wa.Kd[e] / 32);
        wa.start[e + 1] = acc0;
    }
    ws_all<<<acc0, dim3(32, 8)>>>(wa);

    // LN1 -> bf16 (also zero-inits x2 for the WO split-K accumulate)
    ln_kernel<0><<<NROW, 256>>>(x, thi, ln1a, ln1b, x2);

    // Q/K/V projections (bf16, z-batched)
    GemmArgs aq = {};
    aq.A = thi;
    aq.B0 = wqhi; aq.B1 = wkhi; aq.B2 = wvhi;
    aq.S0 = qb; aq.S1 = kb; aq.S2 = vb;
    aq.N = DD; aq.K = DD; aq.splitk = 1;
    mma_gemm<0><<<dim3(DD / 128, NROW / 128, 3), 256, GSMEM>>>(aq);

    // attention -> bf16 context (128 queries / CTA)
    flash_mma<<<dim3(BB * HH, SS / 128), 256, FSMEM>>>(qb, kb, vb, mask, chi);

    // x2 = x + ctx @ wo (bf16, split-K=3, atomic accumulate)
    GemmArgs ao = {};
    ao.A = chi;
    ao.B0 = wohi;
    ao.C0 = x2;
    ao.res = x;
    ao.N = DD; ao.K = DD; ao.splitk = 3;
    mma_gemm<0><<<dim3(DD / 128, NROW / 128, 3), 256, GSMEM>>>(ao);

    // LN2 -> fp16 (also zero-inits out for the FFN2 split-K accumulate)
    ln_kernel<1><<<NROW, 256>>>(x2, t16, ln2a, ln2b, out);

    // FFN1: h1 = relu(t @ w1 + b1) (fp16)
    GemmArgs a1 = {};
    a1.A = t16;
    a1.B0 = w1h;
    a1.bias = b1; a1.relu = 1;
    a1.S0 = h1;
    a1.N = FF; a1.K = DD; a1.splitk = 1;
    mma_gemm<1><<<dim3(FF / 128, NROW / 128, 1), 256, GSMEM>>>(a1);

    // FFN2: out = x2 + h1 @ w2 + b2 (fp16, split-K=3, atomic accumulate)
    GemmArgs a2 = {};
    a2.A = h1;
    a2.B0 = w2h;
    a2.C0 = out;
    a2.bias = b2; a2.res = x2;
    a2.N = DD; a2.K = FF; a2.splitk = 3;
    mma_gemm<1><<<dim3(DD / 128, NROW / 128, 3), 256, GSMEM>>>(a2);
}

// round 14
// speedup vs baseline: 1.2450x; 1.0098x over previous
#include <cuda_runtime.h>
#include <cuda_bf16.h>
#include <cuda_fp16.h>
#include <cstdint>
#include <math.h>

#define BB 2
#define SS 2048
#define DD 768
#define FF 3072
#define HH 12
#define DKK 64
#define NROW (BB*SS)   // 4096

// ---------------------------------------------------------------- scratch
__device__ __nv_bfloat16 g_thi[NROW*DD];
__device__ __half        g_t16[NROW*DD];
__device__ __nv_bfloat16 g_qb[NROW*DD], g_kb[NROW*DD], g_vb[NROW*DD];
__device__ float g_x2[NROW*DD];
__device__ __nv_bfloat16 g_chi[NROW*DD];
__device__ __half        g_h1[NROW*FF];
__device__ __nv_bfloat16 g_wqhi[DD*DD];
__device__ __nv_bfloat16 g_wkhi[DD*DD];
__device__ __nv_bfloat16 g_wvhi[DD*DD];
__device__ __nv_bfloat16 g_wohi[DD*DD];
__device__ __half        g_w1h[FF*DD];   // [F,D] = w1^T (fp16)
__device__ __half        g_w2h[DD*FF];   // [D,F] = w2^T (fp16)

// ---------------------------------------------------------------- helpers
__device__ __forceinline__ uint32_t smem_to_u32(const void* p) {
    uint32_t a;
    asm("{ .reg .u64 t; cvta.to.shared.u64 t, %1; cvt.u32.u64 %0, t; }" : "=r"(a) : "l"(p));
    return a;
}
__device__ __forceinline__ void ldsm_x4(uint32_t (&r)[4], uint32_t addr) {
    asm volatile("ldmatrix.sync.aligned.m8n8.x4.shared.b16 {%0,%1,%2,%3}, [%4];"
                 : "=r"(r[0]), "=r"(r[1]), "=r"(r[2]), "=r"(r[3]) : "r"(addr));
}
__device__ __forceinline__ void ldsm_x4_t(uint32_t (&r)[4], uint32_t addr) {
    asm volatile("ldmatrix.sync.aligned.m8n8.x4.trans.shared.b16 {%0,%1,%2,%3}, [%4];"
                 : "=r"(r[0]), "=r"(r[1]), "=r"(r[2]), "=r"(r[3]) : "r"(addr));
}
__device__ __forceinline__ void mma_bf16(float (&c)[4], const uint32_t (&a)[4], const uint32_t (&b)[2]) {
    asm volatile("mma.sync.aligned.m16n8k16.row.col.f32.bf16.bf16.f32 "
                 "{%0,%1,%2,%3}, {%4,%5,%6,%7}, {%8,%9}, {%0,%1,%2,%3};"
                 : "+f"(c[0]), "+f"(c[1]), "+f"(c[2]), "+f"(c[3])
                 : "r"(a[0]), "r"(a[1]), "r"(a[2]), "r"(a[3]), "r"(b[0]), "r"(b[1]));
}
__device__ __forceinline__ void mma_f16(float (&c)[4], const uint32_t (&a)[4], const uint32_t (&b)[2]) {
    asm volatile("mma.sync.aligned.m16n8k16.row.col.f32.f16.f16.f32 "
                 "{%0,%1,%2,%3}, {%4,%5,%6,%7}, {%8,%9}, {%0,%1,%2,%3};"
                 : "+f"(c[0]), "+f"(c[1]), "+f"(c[2]), "+f"(c[3])
                 : "r"(a[0]), "r"(a[1]), "r"(a[2]), "r"(a[3]), "r"(b[0]), "r"(b[1]));
}
__device__ __forceinline__ void cp16(uint32_t dst, const void* src) {
    asm volatile("cp.async.cg.shared.global [%0], [%1], 16;" :: "r"(dst), "l"(src));
}
#define CP_COMMIT() asm volatile("cp.async.commit_group;" ::: "memory")
#define CP_WAIT1()  asm volatile("cp.async.wait_group 1;" ::: "memory")
#define CP_WAIT0()  asm volatile("cp.async.wait_group 0;" ::: "memory")

__device__ __forceinline__ uint32_t cvt_bf2(float lo, float hi) {
    uint32_t r;
    asm("cvt.rn.bf16x2.f32 %0, %1, %2;" : "=r"(r) : "f"(hi), "f"(lo));
    return r;
}

template<int DT> struct Elem    { using T = __nv_bfloat16; };
template<>       struct Elem<1> { using T = __half; };

template<int DT>
__device__ __forceinline__ void mma_t(float (&c)[4], const uint32_t (&a)[4], const uint32_t (&b)[2]) {
    if constexpr (DT == 0) mma_bf16(c, a, b); else mma_f16(c, a, b);
}
template<int DT>
__device__ __forceinline__ uint32_t pack_t(float x, float y) {
    if constexpr (DT == 0) {
        return cvt_bf2(x, y);
    } else {
        __half2 h = __floats2half2_rn(x, y);
        return *(uint32_t*)&h;
    }
}

// ---------------------------------------------------------------- LayerNorm -> T (single pass; optional row-zeroing of zbuf)
template<int DT>
__global__ void ln_kernel(const float* __restrict__ x,
                          typename Elem<DT>::T* __restrict__ hi,
                          const float* __restrict__ alpha_p, const float* __restrict__ bias_p,
                          float* __restrict__ zbuf)
{
    const int row = blockIdx.x;
    const float* xr = x + (size_t)row * DD;
    const int tid = threadIdx.x, lane = tid & 31, wid = tid >> 5;
    __shared__ float red[8], red2[8];
    __shared__ float s_mean, s_scale;

    if (zbuf) {
        float* zr = zbuf + (size_t)row * DD;
        for (int i = tid; i < DD; i += 256) zr[i] = 0.f;
    }

    float v0 = xr[tid], v1 = xr[tid + 256], v2 = xr[tid + 512];
    float s  = v0 + v1 + v2;
    float s2 = v0 * v0 + v1 * v1 + v2 * v2;
    #pragma unroll
    for (int o = 16; o; o >>= 1) {
        s  += __shfl_xor_sync(0xffffffffu, s, o);
        s2 += __shfl_xor_sync(0xffffffffu, s2, o);
    }
    if (lane == 0) { red[wid] = s; red2[wid] = s2; }
    __syncthreads();
    if (tid == 0) {
        float t = 0.f, t2 = 0.f;
        #pragma unroll
        for (int i = 0; i < 8; i++) { t += red[i]; t2 += red2[i]; }
        const float mean = t / (float)DD;
        const float var = (t2 - (float)DD * mean * mean) / (float)(DD - 1);
        s_mean = mean;
        s_scale = alpha_p[0] / (sqrtf(fmaxf(var, 0.f)) + 1e-6f);
    }
    __syncthreads();
    const float mean = s_mean, scale = s_scale, bias = bias_p[0];

    float y0 = (v0 - mean) * scale + bias;
    float y1 = (v1 - mean) * scale + bias;
    float y2 = (v2 - mean) * scale + bias;
    if constexpr (DT == 0) {
        hi[(size_t)row * DD + tid]       = __float2bfloat16(y0);
        hi[(size_t)row * DD + tid + 256] = __float2bfloat16(y1);
        hi[(size_t)row * DD + tid + 512] = __float2bfloat16(y2);
    } else {
        hi[(size_t)row * DD + tid]       = __float2half(y0);
        hi[(size_t)row * DD + tid + 256] = __float2half(y1);
        hi[(size_t)row * DD + tid + 512] = __float2half(y2);
    }
}

// ---------------------------------------------------------------- merged prologue: weight transpose (6 tensors) + LN1
struct WSArgs {
    const float* W[6];
    void* Hi[6];
    int dt[6];
    int Kd[6], Nd[6];
    int start[7];   // start[6] = total ws blocks
};

__global__ void prolog_kernel(WSArgs a,
                              const float* __restrict__ x,
                              __nv_bfloat16* __restrict__ thi,
                              const float* __restrict__ alpha_p, const float* __restrict__ bias_p,
                              float* __restrict__ zbuf)
{
    __shared__ float t[32][33];
    __shared__ float red[8], red2[8];
    __shared__ float s_mean, s_scale;

    const int tid = threadIdx.x;
    int bidx = blockIdx.x;

    if (bidx < a.start[6]) {
        // ---- weight transpose/convert branch
        int e = 0;
        while (bidx >= a.start[e + 1]) e++;
        const int rel = bidx - a.start[e];
        const int Kd = a.Kd[e], Nd = a.Nd[e];
        const int nx = Nd / 32;
        const int n0 = (rel % nx) * 32, k0 = (rel / nx) * 32;
        const float* W = a.W[e];
        void* Hi = a.Hi[e];
        const int dt = a.dt[e];

        const int tx = tid & 31, ty = tid >> 5;   // 32x8
        #pragma unroll
        for (int r = 0; r < 4; r++)
            t[ty + 8 * r][tx] = W[(size_t)(k0 + ty + 8 * r) * Nd + n0 + tx];
        __syncthreads();
        #pragma unroll
        for (int r = 0; r < 4; r++) {
            float v = t[tx][ty + 8 * r];
            size_t o = (size_t)(n0 + ty + 8 * r) * Kd + k0 + tx;
            if (dt == 0) ((__nv_bfloat16*)Hi)[o] = __float2bfloat16(v);
            else         ((__half*)Hi)[o]        = __float2half(v);
        }
        return;
    }

    // ---- LN1 branch (row = bidx - ws_total), also zero x2 row
    const int row = bidx - a.start[6];
    const float* xr = x + (size_t)row * DD;
    const int lane = tid & 31, wid = tid >> 5;

    {
        float* zr = zbuf + (size_t)row * DD;
        for (int i = tid; i < DD; i += 256) zr[i] = 0.f;
    }

    float v0 = xr[tid], v1 = xr[tid + 256], v2 = xr[tid + 512];
    float s  = v0 + v1 + v2;
    float s2 = v0 * v0 + v1 * v1 + v2 * v2;
    #pragma unroll
    for (int o = 16; o; o >>= 1) {
        s  += __shfl_xor_sync(0xffffffffu, s, o);
        s2 += __shfl_xor_sync(0xffffffffu, s2, o);
    }
    if (lane == 0) { red[wid] = s; red2[wid] = s2; }
    __syncthreads();
    if (tid == 0) {
        float tt = 0.f, t2 = 0.f;
        #pragma unroll
        for (int i = 0; i < 8; i++) { tt += red[i]; t2 += red2[i]; }
        const float mean = tt / (float)DD;
        const float var = (t2 - (float)DD * mean * mean) / (float)(DD - 1);
        s_mean = mean;
        s_scale = alpha_p[0] / (sqrtf(fmaxf(var, 0.f)) + 1e-6f);
    }
    __syncthreads();
    const float mean = s_mean, scale = s_scale, bias = bias_p[0];

    thi[(size_t)row * DD + tid]       = __float2bfloat16((v0 - mean) * scale + bias);
    thi[(size_t)row * DD + tid + 256] = __float2bfloat16((v1 - mean) * scale + bias);
    thi[(size_t)row * DD + tid + 512] = __float2bfloat16((v2 - mean) * scale + bias);
}

// ---------------------------------------------------------------- HMMA GEMM: 8 warps, warp tile 64x32, 2-stage K64
// C = A @ B^T, B given [N,K]; DT: 0=bf16, 1=fp16. 16 warps/SM via 2 CTAs.
// splitk > 1: blockIdx.z indexes a K-partition; partials atomicAdd into
// zero-initialized C; partition 0 carries bias (+res).
struct GemmArgs {
    const void *A;
    const void *B0, *B1, *B2;
    float *C0, *C1, *C2;
    const float *bias, *res;
    void *S0, *S1, *S2;          // optional T outputs (not valid with splitk)
    int relu, N, K, splitk;
};

#define GP 144                        // row pitch bytes for 64-elem (128B) rows
#define GTILE (128 * GP)              // 18432
#define GSTG  (2 * GTILE)             // 36864 (A + B)
#define GSMEM (2 * GSTG)              // 73728 (2 stages)

template<int DT>
__global__ void __launch_bounds__(256, 2) mma_gemm(GemmArgs ga)
{
    using T = typename Elem<DT>::T;
    extern __shared__ char smc[];
    const uint32_t smb = smem_to_u32(smc);
    const int tid = threadIdx.x, wid = tid >> 5, lane = tid & 31;
    const int bn = blockIdx.x * 128, bm = blockIdx.y * 128;
    const int z = blockIdx.z;
    const int sk = ga.splitk;
    const T* A = (const T*)ga.A;
    const T* B; float* C; T* Sh;
    int c0, NC;
    if (sk > 1) {
        B = (const T*)ga.B0; C = ga.C0; Sh = nullptr;
        NC = ga.K / 64 / sk;
        c0 = z * NC;
    } else {
        B = (const T*)((z == 0) ? ga.B0 : ((z == 1) ? ga.B1 : ga.B2));
        C = (z == 0) ? ga.C0 : ((z == 1) ? ga.C1 : ga.C2);
        Sh = (T*)((z == 0) ? ga.S0 : ((z == 1) ? ga.S1 : ga.S2));
        NC = ga.K / 64;
        c0 = 0;
    }
    const int K = ga.K;

    const int wm64 = (wid & 1) * 64;       // 2 warps over M
    const int wn32 = (wid >> 1) * 32;      // 4 warps over N

    float acc[4][4][4];
    #pragma unroll
    for (int f = 0; f < 4; f++)
        #pragma unroll
        for (int n = 0; n < 4; n++)
            #pragma unroll
            for (int e = 0; e < 4; e++) acc[f][n][e] = 0.f;

    auto issue = [&](int c) {
        const int ks = (c0 + c) * 64;
        const uint32_t base = smb + (uint32_t)(c & 1) * GSTG;
        #pragma unroll
        for (int i = 0; i < 8; i++) {
            const int u = tid + i * 256;                 // 0..2047
            const int row = (u >> 3) & 127, c16 = u & 7;
            const uint32_t dst = base + ((u < 1024) ? 0u : (uint32_t)GTILE)
                               + row * GP + c16 * 16;
            const T* src = (u < 1024)
                ? (A + (size_t)(bm + row) * K + ks + c16 * 8)
                : (B + (size_t)(bn + row) * K + ks + c16 * 8);
            cp16(dst, src);
        }
        CP_COMMIT();
    };

    issue(0);
    if (NC > 1) issue(1);

    const uint32_t aBase0 = smb + (uint32_t)((wm64 + (lane & 15)) * GP + ((lane >> 4) << 3) * 2);
    const uint32_t bBase0 = smb + (uint32_t)GTILE
                          + (uint32_t)((wn32 + ((lane >> 4) << 3) + (lane & 7)) * GP
                                       + (((lane >> 3) & 1) << 3) * 2);

    for (int c = 0; c < NC; c++) {
        if (c + 1 < NC) { CP_WAIT1(); } else { CP_WAIT0(); }
        __syncthreads();

        const uint32_t stg = (uint32_t)(c & 1) * GSTG;
        uint32_t aAddr = aBase0 + stg;
        uint32_t bAddr = bBase0 + stg;
        #pragma unroll
        for (int kk = 0; kk < 4; kk++) {
            uint32_t af[4][4];
            #pragma unroll
            for (int f = 0; f < 4; f++)
                ldsm_x4(af[f], aAddr + (uint32_t)(f * 16 * GP));
            uint32_t bq[2][4];
            #pragma unroll
            for (int p = 0; p < 2; p++)
                ldsm_x4(bq[p], bAddr + (uint32_t)(p * 16 * GP));
            aAddr += 32;
            bAddr += 32;
            #pragma unroll
            for (int f = 0; f < 4; f++) {
                #pragma unroll
                for (int p = 0; p < 2; p++) {
                    uint32_t b0[2] = { bq[p][0], bq[p][1] };
                    uint32_t b1[2] = { bq[p][2], bq[p][3] };
                    mma_t<DT>(acc[f][2 * p],     af[f], b0);
                    mma_t<DT>(acc[f][2 * p + 1], af[f], b1);
                }
            }
        }
        __syncthreads();                     // buffer (c&1) free for reuse
        if (c + 2 < NC) issue(c + 2);
    }

    // ---- epilogue
    const int gq = lane >> 2, t4 = lane & 3;
    const bool lead = (sk <= 1) || (z == 0);
    #pragma unroll
    for (int f = 0; f < 4; f++) {
        #pragma unroll
        for (int half = 0; half < 2; half++) {
            const int m = bm + wm64 + f * 16 + gq + half * 8;
            const size_t rowo = (size_t)m * ga.N;
            #pragma unroll
            for (int n = 0; n < 4; n++) {
                const int col = bn + wn32 + n * 8 + t4 * 2;
                float vx = acc[f][n][half * 2 + 0];
                float vy = acc[f][n][half * 2 + 1];
                if (ga.bias && lead) {
                    float2 bb = *(const float2*)(ga.bias + col);
                    vx += bb.x; vy += bb.y;
                }
                if (ga.relu) { vx = fmaxf(vx, 0.f); vy = fmaxf(vy, 0.f); }
                if (ga.res && lead) {
                    float2 rr = *(const float2*)(ga.res + rowo + col);
                    vx += rr.x; vy += rr.y;
                }
                if (sk > 1) {
                    atomicAdd(C + rowo + col,     vx);
                    atomicAdd(C + rowo + col + 1, vy);
                } else if (Sh) {
                    *(uint32_t*)(Sh + rowo + col) = pack_t<DT>(vx, vy);
                } else {
                    *(float2*)(C + rowo + col) = make_float2(vx, vy);
                }
            }
        }
    }
}

// ---------------------------------------------------------------- HMMA flash attention (bf16) — R10 config
#define FPITCH 144
#define FQOFF 0
#define FQSZ  (128 * FPITCH)                 // 18432
#define FKOFF FQSZ
#define FSTG  (2 * 64 * FPITCH)              // 18432 (K + V per stage)
#define FMOFF (FKOFF + 2 * FSTG)             // 55296
#define FSMEM (FMOFF + 512)                  // 55808

__global__ void __launch_bounds__(256, 2) flash_mma(
    const __nv_bfloat16* __restrict__ Qb, const __nv_bfloat16* __restrict__ Kb,
    const __nv_bfloat16* __restrict__ Vb, const int* __restrict__ mask,
    __nv_bfloat16* __restrict__ Ohi)
{
    extern __shared__ char fsm[];
    const uint32_t smb = smem_to_u32(fsm);
    const int tid = threadIdx.x, wid = tid >> 5, lane = tid & 31;
    const int gq = lane >> 2, t4 = lane & 3;
    const int bh = blockIdx.x, b = bh / HH, h = bh % HH;
    const int q0 = blockIdx.y * 128;
    const int NIT = SS / 64;

    auto cpKV = [&](int it, int st) {
        const uint32_t ks = smb + FKOFF + st * FSTG;
        const uint32_t vs = ks + 64 * FPITCH;
        const __nv_bfloat16* Ksrc = Kb + (size_t)(b * SS + it * 64) * DD + h * 64;
        const __nv_bfloat16* Vsrc = Vb + (size_t)(b * SS + it * 64) * DD + h * 64;
        #pragma unroll
        for (int i = 0; i < 2; i++) {
            const int idx = tid + i * 256;                 // 0..511
            const int r = idx >> 3, c = idx & 7;
            cp16(ks + r * FPITCH + c * 16, Ksrc + (size_t)r * DD + c * 8);
            cp16(vs + r * FPITCH + c * 16, Vsrc + (size_t)r * DD + c * 8);
        }
        if (tid < 16)
            cp16(smb + FMOFF + st * 256 + tid * 16, mask + b * SS + it * 64 + tid * 4);
        CP_COMMIT();
    };

    {
        const __nv_bfloat16* Qsrc = Qb + (size_t)(b * SS + q0) * DD + h * 64;
        #pragma unroll
        for (int i = 0; i < 4; i++) {
            const int idx = tid + i * 256;                 // 0..1023
            const int r = idx >> 3, c = idx & 7;
            cp16(smb + FQOFF + r * FPITCH + c * 16, Qsrc + (size_t)r * DD + c * 8);
        }
        const uint32_t ks = smb + FKOFF;
        const uint32_t vs = ks + 64 * FPITCH;
        const __nv_bfloat16* Ksrc = Kb + (size_t)(b * SS) * DD + h * 64;
        const __nv_bfloat16* Vsrc = Vb + (size_t)(b * SS) * DD + h * 64;
        #pragma unroll
        for (int i = 0; i < 2; i++) {
            const int idx = tid + i * 256;
            const int r = idx >> 3, c = idx & 7;
            cp16(ks + r * FPITCH + c * 16, Ksrc + (size_t)r * DD + c * 8);
            cp16(vs + r * FPITCH + c * 16, Vsrc + (size_t)r * DD + c * 8);
        }
        if (tid < 16)
            cp16(smb + FMOFF + tid * 16, mask + b * SS + tid * 4);
        CP_COMMIT();
        cpKV(1, 1);
    }

    CP_WAIT1();
    __syncthreads();

    uint32_t aq[4][4];
    #pragma unroll
    for (int kc = 0; kc < 4; kc++) {
        uint32_t addr = smb + FQOFF
                      + (uint32_t)((wid * 16 + (lane & 15)) * FPITCH
                                   + (kc * 16 + ((lane >> 4) << 3)) * 2);
        ldsm_x4(aq[kc], addr);
    }

    float oacc[8][4];
    #pragma unroll
    for (int n = 0; n < 8; n++)
        #pragma unroll
        for (int e = 0; e < 4; e++) oacc[n][e] = 0.f;
    float l0 = 0.f, l1 = 0.f;

    for (int it = 0; it < NIT; it++) {
        if (it > 0) {
            if (it + 1 < NIT) { CP_WAIT1(); } else { CP_WAIT0(); }
            __syncthreads();
        }
        const int st = it & 1;
        const uint32_t ks = smb + FKOFF + st * FSTG;
        const uint32_t vs = ks + 64 * FPITCH;
        const int* Mi = (const int*)(fsm + FMOFF + st * 256);

        float sacc[8][4];
        #pragma unroll
        for (int j = 0; j < 8; j++)
            #pragma unroll
            for (int e = 0; e < 4; e++) sacc[j][e] = 0.f;

        #pragma unroll
        for (int kc = 0; kc < 4; kc++) {
            uint32_t bfr[4][4];
            #pragma unroll
            for (int jj = 0; jj < 4; jj++) {
                uint32_t addr = ks + (uint32_t)((jj * 16 + ((lane >> 4) << 3) + (lane & 7)) * FPITCH
                                                + (kc * 16 + (((lane >> 3) & 1) << 3)) * 2);
                ldsm_x4(bfr[jj], addr);
            }
            #pragma unroll
            for (int jj = 0; jj < 4; jj++) {
                uint32_t b0[2] = { bfr[jj][0], bfr[jj][1] };
                uint32_t b1[2] = { bfr[jj][2], bfr[jj][3] };
                mma_bf16(sacc[2 * jj],     aq[kc], b0);
                mma_bf16(sacc[2 * jj + 1], aq[kc], b1);
            }
        }

        uint32_t pf[8][2];
        #pragma unroll
        for (int j = 0; j < 8; j++) {
            const int col = j * 8 + t4 * 2;
            const int m0 = Mi[col], m1 = Mi[col + 1];
            float s0 = m0 ? sacc[j][0] * 0.125f : 1e-9f;
            float s1 = m1 ? sacc[j][1] * 0.125f : 1e-9f;
            float s2 = m0 ? sacc[j][2] * 0.125f : 1e-9f;
            float s3 = m1 ? sacc[j][3] * 0.125f : 1e-9f;
            float p0 = __expf(s0), p1 = __expf(s1), p2 = __expf(s2), p3 = __expf(s3);
            l0 += p0 + p1;
            l1 += p2 + p3;
            pf[j][0] = cvt_bf2(p0, p1);
            pf[j][1] = cvt_bf2(p2, p3);
        }

        #pragma unroll
        for (int jk = 0; jk < 4; jk++) {
            uint32_t a[4] = { pf[2 * jk][0], pf[2 * jk][1], pf[2 * jk + 1][0], pf[2 * jk + 1][1] };
            #pragma unroll
            for (int nn = 0; nn < 4; nn++) {
                uint32_t bv[4];
                uint32_t addr = vs + (uint32_t)((jk * 16 + (((lane >> 3) & 1) << 3) + (lane & 7)) * FPITCH
                                                + (nn * 16 + ((lane >> 4) << 3)) * 2);
                ldsm_x4_t(bv, addr);
                uint32_t b0[2] = { bv[0], bv[1] };
                uint32_t b1[2] = { bv[2], bv[3] };
                mma_bf16(oacc[2 * nn],     a, b0);
                mma_bf16(oacc[2 * nn + 1], a, b1);
            }
        }

        __syncthreads();
        if (it + 2 < NIT) cpKV(it + 2, st);
    }

    l0 += __shfl_xor_sync(0xffffffffu, l0, 1);
    l0 += __shfl_xor_sync(0xffffffffu, l0, 2);
    l1 += __shfl_xor_sync(0xffffffffu, l1, 1);
    l1 += __shfl_xor_sync(0xffffffffu, l1, 2);
    const float inv0 = 1.f / l0, inv1 = 1.f / l1;

    const int r0 = b * SS + q0 + wid * 16 + gq;
    const int r1 = r0 + 8;
    #pragma unroll
    for (int nn = 0; nn < 8; nn++) {
        const int col = h * 64 + nn * 8 + t4 * 2;
        *(uint32_t*)(Ohi + (size_t)r0 * DD + col) =
            cvt_bf2(oacc[nn][0] * inv0, oacc[nn][1] * inv0);
        *(uint32_t*)(Ohi + (size_t)r1 * DD + col) =
            cvt_bf2(oacc[nn][2] * inv1, oacc[nn][3] * inv1);
    }
}

// ---------------------------------------------------------------- launch
extern "C" void kernel_launch(void* const* d_in, const int* in_sizes, int n_in,
                              void* d_out, int out_size)
{
    const float* x    = (const float*)d_in[0];
    const int*   mask = (const int*)  d_in[1];
    const float* wq   = (const float*)d_in[2];
    const float* wk   = (const float*)d_in[3];
    const float* wv   = (const float*)d_in[4];
    const float* wo   = (const float*)d_in[5];
    const float* w1   = (const float*)d_in[6];
    const float* b1   = (const float*)d_in[7];
    const float* w2   = (const float*)d_in[8];
    const float* b2   = (const float*)d_in[9];
    const float* ln1a = (const float*)d_in[10];
    const float* ln1b = (const float*)d_in[11];
    const float* ln2a = (const float*)d_in[12];
    const float* ln2b = (const float*)d_in[13];
    float* out = (float*)d_out;

    __nv_bfloat16 *thi, *chi, *qb, *kb, *vb;
    __nv_bfloat16 *wqhi, *wkhi, *wvhi, *wohi;
    __half *t16, *h1, *w1h, *w2h;
    float *x2;
    cudaGetSymbolAddress((void**)&thi, g_thi);
    cudaGetSymbolAddress((void**)&t16, g_t16);
    cudaGetSymbolAddress((void**)&chi, g_chi);
    cudaGetSymbolAddress((void**)&h1, g_h1);
    cudaGetSymbolAddress((void**)&qb, g_qb);     cudaGetSymbolAddress((void**)&kb, g_kb);
    cudaGetSymbolAddress((void**)&vb, g_vb);
    cudaGetSymbolAddress((void**)&wqhi, g_wqhi);
    cudaGetSymbolAddress((void**)&wkhi, g_wkhi);
    cudaGetSymbolAddress((void**)&wvhi, g_wvhi);
    cudaGetSymbolAddress((void**)&wohi, g_wohi);
    cudaGetSymbolAddress((void**)&w1h, g_w1h);
    cudaGetSymbolAddress((void**)&w2h, g_w2h);
    cudaGetSymbolAddress((void**)&x2, g_x2);

    cudaFuncSetAttribute(mma_gemm<0>, cudaFuncAttributeMaxDynamicSharedMemorySize, GSMEM);
    cudaFuncSetAttribute(mma_gemm<1>, cudaFuncAttributeMaxDynamicSharedMemorySize, GSMEM);
    cudaFuncSetAttribute(flash_mma, cudaFuncAttributeMaxDynamicSharedMemorySize, FSMEM);

    // merged prologue: weight transpose (bf16 q/k/v/o; fp16 w1/w2) + LN1 (+x2 zero)
    WSArgs wa = {};
    wa.W[0] = wq; wa.Hi[0] = wqhi; wa.dt[0] = 0; wa.Kd[0] = DD; wa.Nd[0] = DD;
    wa.W[1] = wk; wa.Hi[1] = wkhi; wa.dt[1] = 0; wa.Kd[1] = DD; wa.Nd[1] = DD;
    wa.W[2] = wv; wa.Hi[2] = wvhi; wa.dt[2] = 0; wa.Kd[2] = DD; wa.Nd[2] = DD;
    wa.W[3] = wo; wa.Hi[3] = wohi; wa.dt[3] = 0; wa.Kd[3] = DD; wa.Nd[3] = DD;
    wa.W[4] = w1; wa.Hi[4] = w1h;  wa.dt[4] = 1; wa.Kd[4] = DD; wa.Nd[4] = FF;
    wa.W[5] = w2; wa.Hi[5] = w2h;  wa.dt[5] = 1; wa.Kd[5] = FF; wa.Nd[5] = DD;
    int acc0 = 0;
    wa.start[0] = 0;
    for (int e = 0; e < 6; e++) {
        acc0 += (wa.Nd[e] / 32) * (wa.Kd[e] / 32);
        wa.start[e + 1] = acc0;
    }
    prolog_kernel<<<acc0 + NROW, 256>>>(wa, x, thi, ln1a, ln1b, x2);

    // Q/K/V projections (bf16, z-batched)
    GemmArgs aq = {};
    aq.A = thi;
    aq.B0 = wqhi; aq.B1 = wkhi; aq.B2 = wvhi;
    aq.S0 = qb; aq.S1 = kb; aq.S2 = vb;
    aq.N = DD; aq.K = DD; aq.splitk = 1;
    mma_gemm<0><<<dim3(DD / 128, NROW / 128, 3), 256, GSMEM>>>(aq);

    // attention -> bf16 context (128 queries / CTA)
    flash_mma<<<dim3(BB * HH, SS / 128), 256, FSMEM>>>(qb, kb, vb, mask, chi);

    // x2 = x + ctx @ wo (bf16, split-K=3, atomic accumulate)
    GemmArgs ao = {};
    ao.A = chi;
    ao.B0 = wohi;
    ao.C0 = x2;
    ao.res = x;
    ao.N = DD; ao.K = DD; ao.splitk = 3;
    mma_gemm<0><<<dim3(DD / 128, NROW / 128, 3), 256, GSMEM>>>(ao);

    // LN2 -> fp16 (also zero-inits out for the FFN2 split-K accumulate)
    ln_kernel<1><<<NROW, 256>>>(x2, t16, ln2a, ln2b, out);

    // FFN1: h1 = relu(t @ w1 + b1) (fp16)
    GemmArgs a1 = {};
    a1.A = t16;
    a1.B0 = w1h;
    a1.bias = b1; a1.relu = 1;
    a1.S0 = h1;
    a1.N = FF; a1.K = DD; a1.splitk = 1;
    mma_gemm<1><<<dim3(FF / 128, NROW / 128, 1), 256, GSMEM>>>(a1);

    // FFN2: out = x2 + h1 @ w2 + b2 (fp16, split-K=3, atomic accumulate)
    GemmArgs a2 = {};
    a2.A = h1;
    a2.B0 = w2h;
    a2.C0 = out;
    a2.bias = b2; a2.res = x2;
    a2.N = DD; a2.K = FF; a2.splitk = 3;
    mma_gemm<1><<<dim3(DD / 128, NROW / 128, 3), 256, GSMEM>>>(a2);
}

// round 15
// speedup vs baseline: 1.2713x; 1.0212x over previous
#include <cuda_runtime.h>
#include <cuda_bf16.h>
#include <cuda_fp16.h>
#include <cstdint>
#include <math.h>

#define BB 2
#define SS 2048
#define DD 768
#define FF 3072
#define HH 12
#define DKK 64
#define NROW (BB*SS)   // 4096

// ---------------------------------------------------------------- scratch
__device__ __nv_bfloat16 g_thi[NROW*DD];
__device__ __half        g_t16[NROW*DD];
__device__ __nv_bfloat16 g_qb[NROW*DD], g_kb[NROW*DD], g_vb[NROW*DD];
__device__ float g_x2[NROW*DD];
__device__ __nv_bfloat16 g_chi[NROW*DD];
__device__ __half        g_h1[NROW*FF];
__device__ __nv_bfloat16 g_wqhi[DD*DD];
__device__ __nv_bfloat16 g_wkhi[DD*DD];
__device__ __nv_bfloat16 g_wvhi[DD*DD];
__device__ __nv_bfloat16 g_wohi[DD*DD];
__device__ __half        g_w1h[FF*DD];   // [F,D] = w1^T (fp16)
__device__ __half        g_w2h[DD*FF];   // [D,F] = w2^T (fp16)

// ---------------------------------------------------------------- helpers
__device__ __forceinline__ uint32_t smem_to_u32(const void* p) {
    uint32_t a;
    asm("{ .reg .u64 t; cvta.to.shared.u64 t, %1; cvt.u32.u64 %0, t; }" : "=r"(a) : "l"(p));
    return a;
}
__device__ __forceinline__ void ldsm_x4(uint32_t (&r)[4], uint32_t addr) {
    asm volatile("ldmatrix.sync.aligned.m8n8.x4.shared.b16 {%0,%1,%2,%3}, [%4];"
                 : "=r"(r[0]), "=r"(r[1]), "=r"(r[2]), "=r"(r[3]) : "r"(addr));
}
__device__ __forceinline__ void ldsm_x4_t(uint32_t (&r)[4], uint32_t addr) {
    asm volatile("ldmatrix.sync.aligned.m8n8.x4.trans.shared.b16 {%0,%1,%2,%3}, [%4];"
                 : "=r"(r[0]), "=r"(r[1]), "=r"(r[2]), "=r"(r[3]) : "r"(addr));
}
__device__ __forceinline__ void mma_bf16(float (&c)[4], const uint32_t (&a)[4], const uint32_t (&b)[2]) {
    asm volatile("mma.sync.aligned.m16n8k16.row.col.f32.bf16.bf16.f32 "
                 "{%0,%1,%2,%3}, {%4,%5,%6,%7}, {%8,%9}, {%0,%1,%2,%3};"
                 : "+f"(c[0]), "+f"(c[1]), "+f"(c[2]), "+f"(c[3])
                 : "r"(a[0]), "r"(a[1]), "r"(a[2]), "r"(a[3]), "r"(b[0]), "r"(b[1]));
}
__device__ __forceinline__ void mma_f16(float (&c)[4], const uint32_t (&a)[4], const uint32_t (&b)[2]) {
    asm volatile("mma.sync.aligned.m16n8k16.row.col.f32.f16.f16.f32 "
                 "{%0,%1,%2,%3}, {%4,%5,%6,%7}, {%8,%9}, {%0,%1,%2,%3};"
                 : "+f"(c[0]), "+f"(c[1]), "+f"(c[2]), "+f"(c[3])
                 : "r"(a[0]), "r"(a[1]), "r"(a[2]), "r"(a[3]), "r"(b[0]), "r"(b[1]));
}
__device__ __forceinline__ void cp16(uint32_t dst, const void* src) {
    asm volatile("cp.async.cg.shared.global [%0], [%1], 16;" :: "r"(dst), "l"(src));
}
#define CP_COMMIT() asm volatile("cp.async.commit_group;" ::: "memory")
#define CP_WAIT1()  asm volatile("cp.async.wait_group 1;" ::: "memory")
#define CP_WAIT0()  asm volatile("cp.async.wait_group 0;" ::: "memory")

__device__ __forceinline__ uint32_t cvt_bf2(float lo, float hi) {
    uint32_t r;
    asm("cvt.rn.bf16x2.f32 %0, %1, %2;" : "=r"(r) : "f"(hi), "f"(lo));
    return r;
}
__device__ __forceinline__ void red_add2(float* addr, float vx, float vy) {
    asm volatile("red.global.add.v2.f32 [%0], {%1, %2};"
                 :: "l"(addr), "f"(vx), "f"(vy) : "memory");
}

template<int DT> struct Elem    { using T = __nv_bfloat16; };
template<>       struct Elem<1> { using T = __half; };

template<int DT>
__device__ __forceinline__ void mma_t(float (&c)[4], const uint32_t (&a)[4], const uint32_t (&b)[2]) {
    if constexpr (DT == 0) mma_bf16(c, a, b); else mma_f16(c, a, b);
}
template<int DT>
__device__ __forceinline__ uint32_t pack_t(float x, float y) {
    if constexpr (DT == 0) {
        return cvt_bf2(x, y);
    } else {
        __half2 h = __floats2half2_rn(x, y);
        return *(uint32_t*)&h;
    }
}

// ---------------------------------------------------------------- LayerNorm -> T
// zbuf (optional): initialized to x + zbias (residual/bias pre-seed for split-K reds)
template<int DT>
__global__ void ln_kernel(const float* __restrict__ x,
                          typename Elem<DT>::T* __restrict__ hi,
                          const float* __restrict__ alpha_p, const float* __restrict__ bias_p,
                          float* __restrict__ zbuf, const float* __restrict__ zbias)
{
    const int row = blockIdx.x;
    const float* xr = x + (size_t)row * DD;
    const int tid = threadIdx.x, lane = tid & 31, wid = tid >> 5;
    __shared__ float red[8], red2[8];
    __shared__ float s_mean, s_scale;

    float v0 = xr[tid], v1 = xr[tid + 256], v2 = xr[tid + 512];

    if (zbuf) {
        float* zr = zbuf + (size_t)row * DD;
        zr[tid]       = v0 + (zbias ? zbias[tid]       : 0.f);
        zr[tid + 256] = v1 + (zbias ? zbias[tid + 256] : 0.f);
        zr[tid + 512] = v2 + (zbias ? zbias[tid + 512] : 0.f);
    }

    float s  = v0 + v1 + v2;
    float s2 = v0 * v0 + v1 * v1 + v2 * v2;
    #pragma unroll
    for (int o = 16; o; o >>= 1) {
        s  += __shfl_xor_sync(0xffffffffu, s, o);
        s2 += __shfl_xor_sync(0xffffffffu, s2, o);
    }
    if (lane == 0) { red[wid] = s; red2[wid] = s2; }
    __syncthreads();
    if (tid == 0) {
        float t = 0.f, t2 = 0.f;
        #pragma unroll
        for (int i = 0; i < 8; i++) { t += red[i]; t2 += red2[i]; }
        const float mean = t / (float)DD;
        const float var = (t2 - (float)DD * mean * mean) / (float)(DD - 1);
        s_mean = mean;
        s_scale = alpha_p[0] / (sqrtf(fmaxf(var, 0.f)) + 1e-6f);
    }
    __syncthreads();
    const float mean = s_mean, scale = s_scale, bias = bias_p[0];

    float y0 = (v0 - mean) * scale + bias;
    float y1 = (v1 - mean) * scale + bias;
    float y2 = (v2 - mean) * scale + bias;
    if constexpr (DT == 0) {
        hi[(size_t)row * DD + tid]       = __float2bfloat16(y0);
        hi[(size_t)row * DD + tid + 256] = __float2bfloat16(y1);
        hi[(size_t)row * DD + tid + 512] = __float2bfloat16(y2);
    } else {
        hi[(size_t)row * DD + tid]       = __float2half(y0);
        hi[(size_t)row * DD + tid + 256] = __float2half(y1);
        hi[(size_t)row * DD + tid + 512] = __float2half(y2);
    }
}

// ---------------------------------------------------------------- merged prologue: weight transpose (6 tensors) + LN1
struct WSArgs {
    const float* W[6];
    void* Hi[6];
    int dt[6];
    int Kd[6], Nd[6];
    int start[7];   // start[6] = total ws blocks
};

__global__ void prolog_kernel(WSArgs a,
                              const float* __restrict__ x,
                              __nv_bfloat16* __restrict__ thi,
                              const float* __restrict__ alpha_p, const float* __restrict__ bias_p,
                              float* __restrict__ zbuf)
{
    __shared__ float t[32][33];
    __shared__ float red[8], red2[8];
    __shared__ float s_mean, s_scale;

    const int tid = threadIdx.x;
    int bidx = blockIdx.x;

    if (bidx < a.start[6]) {
        // ---- weight transpose/convert branch
        int e = 0;
        while (bidx >= a.start[e + 1]) e++;
        const int rel = bidx - a.start[e];
        const int Kd = a.Kd[e], Nd = a.Nd[e];
        const int nx = Nd / 32;
        const int n0 = (rel % nx) * 32, k0 = (rel / nx) * 32;
        const float* W = a.W[e];
        void* Hi = a.Hi[e];
        const int dt = a.dt[e];

        const int tx = tid & 31, ty = tid >> 5;   // 32x8
        #pragma unroll
        for (int r = 0; r < 4; r++)
            t[ty + 8 * r][tx] = W[(size_t)(k0 + ty + 8 * r) * Nd + n0 + tx];
        __syncthreads();
        #pragma unroll
        for (int r = 0; r < 4; r++) {
            float v = t[tx][ty + 8 * r];
            size_t o = (size_t)(n0 + ty + 8 * r) * Kd + k0 + tx;
            if (dt == 0) ((__nv_bfloat16*)Hi)[o] = __float2bfloat16(v);
            else         ((__half*)Hi)[o]        = __float2half(v);
        }
        return;
    }

    // ---- LN1 branch; seed x2 row with x (residual pre-add for WO split-K)
    const int row = bidx - a.start[6];
    const float* xr = x + (size_t)row * DD;
    const int lane = tid & 31, wid = tid >> 5;

    float v0 = xr[tid], v1 = xr[tid + 256], v2 = xr[tid + 512];
    {
        float* zr = zbuf + (size_t)row * DD;
        zr[tid]       = v0;
        zr[tid + 256] = v1;
        zr[tid + 512] = v2;
    }

    float s  = v0 + v1 + v2;
    float s2 = v0 * v0 + v1 * v1 + v2 * v2;
    #pragma unroll
    for (int o = 16; o; o >>= 1) {
        s  += __shfl_xor_sync(0xffffffffu, s, o);
        s2 += __shfl_xor_sync(0xffffffffu, s2, o);
    }
    if (lane == 0) { red[wid] = s; red2[wid] = s2; }
    __syncthreads();
    if (tid == 0) {
        float tt = 0.f, t2 = 0.f;
        #pragma unroll
        for (int i = 0; i < 8; i++) { tt += red[i]; t2 += red2[i]; }
        const float mean = tt / (float)DD;
        const float var = (t2 - (float)DD * mean * mean) / (float)(DD - 1);
        s_mean = mean;
        s_scale = alpha_p[0] / (sqrtf(fmaxf(var, 0.f)) + 1e-6f);
    }
    __syncthreads();
    const float mean = s_mean, scale = s_scale, bias = bias_p[0];

    thi[(size_t)row * DD + tid]       = __float2bfloat16((v0 - mean) * scale + bias);
    thi[(size_t)row * DD + tid + 256] = __float2bfloat16((v1 - mean) * scale + bias);
    thi[(size_t)row * DD + tid + 512] = __float2bfloat16((v2 - mean) * scale + bias);
}

// ---------------------------------------------------------------- HMMA GEMM: 8 warps, warp tile 64x32, 2-stage K64
// C = A @ B^T, B given [N,K]; DT: 0=bf16, 1=fp16. 16 warps/SM via 2 CTAs.
// splitk > 1: blockIdx.z indexes a K-partition; partials red.v2 into
// pre-seeded C (residual/bias already folded in by the producer kernel).
struct GemmArgs {
    const void *A;
    const void *B0, *B1, *B2;
    float *C0, *C1, *C2;
    const float *bias, *res;
    void *S0, *S1, *S2;          // optional T outputs (not valid with splitk)
    int relu, N, K, splitk;
};

#define GP 144                        // row pitch bytes for 64-elem (128B) rows
#define GTILE (128 * GP)              // 18432
#define GSTG  (2 * GTILE)             // 36864 (A + B)
#define GSMEM (2 * GSTG)              // 73728 (2 stages)

template<int DT>
__global__ void __launch_bounds__(256, 2) mma_gemm(GemmArgs ga)
{
    using T = typename Elem<DT>::T;
    extern __shared__ char smc[];
    const uint32_t smb = smem_to_u32(smc);
    const int tid = threadIdx.x, wid = tid >> 5, lane = tid & 31;
    const int bn = blockIdx.x * 128, bm = blockIdx.y * 128;
    const int z = blockIdx.z;
    const int sk = ga.splitk;
    const T* A = (const T*)ga.A;
    const T* B; float* C; T* Sh;
    int c0, NC;
    if (sk > 1) {
        B = (const T*)ga.B0; C = ga.C0; Sh = nullptr;
        NC = ga.K / 64 / sk;
        c0 = z * NC;
    } else {
        B = (const T*)((z == 0) ? ga.B0 : ((z == 1) ? ga.B1 : ga.B2));
        C = (z == 0) ? ga.C0 : ((z == 1) ? ga.C1 : ga.C2);
        Sh = (T*)((z == 0) ? ga.S0 : ((z == 1) ? ga.S1 : ga.S2));
        NC = ga.K / 64;
        c0 = 0;
    }
    const int K = ga.K;

    const int wm64 = (wid & 1) * 64;       // 2 warps over M
    const int wn32 = (wid >> 1) * 32;      // 4 warps over N

    float acc[4][4][4];
    #pragma unroll
    for (int f = 0; f < 4; f++)
        #pragma unroll
        for (int n = 0; n < 4; n++)
            #pragma unroll
            for (int e = 0; e < 4; e++) acc[f][n][e] = 0.f;

    auto issue = [&](int c) {
        const int ks = (c0 + c) * 64;
        const uint32_t base = smb + (uint32_t)(c & 1) * GSTG;
        #pragma unroll
        for (int i = 0; i < 8; i++) {
            const int u = tid + i * 256;                 // 0..2047
            const int row = (u >> 3) & 127, c16 = u & 7;
            const uint32_t dst = base + ((u < 1024) ? 0u : (uint32_t)GTILE)
                               + row * GP + c16 * 16;
            const T* src = (u < 1024)
                ? (A + (size_t)(bm + row) * K + ks + c16 * 8)
                : (B + (size_t)(bn + row) * K + ks + c16 * 8);
            cp16(dst, src);
        }
        CP_COMMIT();
    };

    issue(0);
    if (NC > 1) issue(1);

    const uint32_t aBase0 = smb + (uint32_t)((wm64 + (lane & 15)) * GP + ((lane >> 4) << 3) * 2);
    const uint32_t bBase0 = smb + (uint32_t)GTILE
                          + (uint32_t)((wn32 + ((lane >> 4) << 3) + (lane & 7)) * GP
                                       + (((lane >> 3) & 1) << 3) * 2);

    for (int c = 0; c < NC; c++) {
        if (c + 1 < NC) { CP_WAIT1(); } else { CP_WAIT0(); }
        __syncthreads();

        const uint32_t stg = (uint32_t)(c & 1) * GSTG;
        uint32_t aAddr = aBase0 + stg;
        uint32_t bAddr = bBase0 + stg;
        #pragma unroll
        for (int kk = 0; kk < 4; kk++) {
            uint32_t af[4][4];
            #pragma unroll
            for (int f = 0; f < 4; f++)
                ldsm_x4(af[f], aAddr + (uint32_t)(f * 16 * GP));
            uint32_t bq[2][4];
            #pragma unroll
            for (int p = 0; p < 2; p++)
                ldsm_x4(bq[p], bAddr + (uint32_t)(p * 16 * GP));
            aAddr += 32;
            bAddr += 32;
            #pragma unroll
            for (int f = 0; f < 4; f++) {
                #pragma unroll
                for (int p = 0; p < 2; p++) {
                    uint32_t b0[2] = { bq[p][0], bq[p][1] };
                    uint32_t b1[2] = { bq[p][2], bq[p][3] };
                    mma_t<DT>(acc[f][2 * p],     af[f], b0);
                    mma_t<DT>(acc[f][2 * p + 1], af[f], b1);
                }
            }
        }
        __syncthreads();                     // buffer (c&1) free for reuse
        if (c + 2 < NC) issue(c + 2);
    }

    // ---- epilogue
    const int gq = lane >> 2, t4 = lane & 3;
    #pragma unroll
    for (int f = 0; f < 4; f++) {
        #pragma unroll
        for (int half = 0; half < 2; half++) {
            const int m = bm + wm64 + f * 16 + gq + half * 8;
            const size_t rowo = (size_t)m * ga.N;
            #pragma unroll
            for (int n = 0; n < 4; n++) {
                const int col = bn + wn32 + n * 8 + t4 * 2;
                float vx = acc[f][n][half * 2 + 0];
                float vy = acc[f][n][half * 2 + 1];
                if (sk > 1) {
                    red_add2(C + rowo + col, vx, vy);      // C pre-seeded with res(+bias)
                    continue;
                }
                if (ga.bias) {
                    float2 bb = *(const float2*)(ga.bias + col);
                    vx += bb.x; vy += bb.y;
                }
                if (ga.relu) { vx = fmaxf(vx, 0.f); vy = fmaxf(vy, 0.f); }
                if (ga.res) {
                    float2 rr = *(const float2*)(ga.res + rowo + col);
                    vx += rr.x; vy += rr.y;
                }
                if (Sh) {
                    *(uint32_t*)(Sh + rowo + col) = pack_t<DT>(vx, vy);
                } else {
                    *(float2*)(C + rowo + col) = make_float2(vx, vy);
                }
            }
        }
    }
}

// ---------------------------------------------------------------- HMMA flash attention (bf16) — R10 config
#define FPITCH 144
#define FQOFF 0
#define FQSZ  (128 * FPITCH)                 // 18432
#define FKOFF FQSZ
#define FSTG  (2 * 64 * FPITCH)              // 18432 (K + V per stage)
#define FMOFF (FKOFF + 2 * FSTG)             // 55296
#define FSMEM (FMOFF + 512)                  // 55808

__global__ void __launch_bounds__(256, 2) flash_mma(
    const __nv_bfloat16* __restrict__ Qb, const __nv_bfloat16* __restrict__ Kb,
    const __nv_bfloat16* __restrict__ Vb, const int* __restrict__ mask,
    __nv_bfloat16* __restrict__ Ohi)
{
    extern __shared__ char fsm[];
    const uint32_t smb = smem_to_u32(fsm);
    const int tid = threadIdx.x, wid = tid >> 5, lane = tid & 31;
    const int gq = lane >> 2, t4 = lane & 3;
    const int bh = blockIdx.x, b = bh / HH, h = bh % HH;
    const int q0 = blockIdx.y * 128;
    const int NIT = SS / 64;

    auto cpKV = [&](int it, int st) {
        const uint32_t ks = smb + FKOFF + st * FSTG;
        const uint32_t vs = ks + 64 * FPITCH;
        const __nv_bfloat16* Ksrc = Kb + (size_t)(b * SS + it * 64) * DD + h * 64;
        const __nv_bfloat16* Vsrc = Vb + (size_t)(b * SS + it * 64) * DD + h * 64;
        #pragma unroll
        for (int i = 0; i < 2; i++) {
            const int idx = tid + i * 256;                 // 0..511
            const int r = idx >> 3, c = idx & 7;
            cp16(ks + r * FPITCH + c * 16, Ksrc + (size_t)r * DD + c * 8);
            cp16(vs + r * FPITCH + c * 16, Vsrc + (size_t)r * DD + c * 8);
        }
        if (tid < 16)
            cp16(smb + FMOFF + st * 256 + tid * 16, mask + b * SS + it * 64 + tid * 4);
        CP_COMMIT();
    };

    {
        const __nv_bfloat16* Qsrc = Qb + (size_t)(b * SS + q0) * DD + h * 64;
        #pragma unroll
        for (int i = 0; i < 4; i++) {
            const int idx = tid + i * 256;                 // 0..1023
            const int r = idx >> 3, c = idx & 7;
            cp16(smb + FQOFF + r * FPITCH + c * 16, Qsrc + (size_t)r * DD + c * 8);
        }
        const uint32_t ks = smb + FKOFF;
        const uint32_t vs = ks + 64 * FPITCH;
        const __nv_bfloat16* Ksrc = Kb + (size_t)(b * SS) * DD + h * 64;
        const __nv_bfloat16* Vsrc = Vb + (size_t)(b * SS) * DD + h * 64;
        #pragma unroll
        for (int i = 0; i < 2; i++) {
            const int idx = tid + i * 256;
            const int r = idx >> 3, c = idx & 7;
            cp16(ks + r * FPITCH + c * 16, Ksrc + (size_t)r * DD + c * 8);
            cp16(vs + r * FPITCH + c * 16, Vsrc + (size_t)r * DD + c * 8);
        }
        if (tid < 16)
            cp16(smb + FMOFF + tid * 16, mask + b * SS + tid * 4);
        CP_COMMIT();
        cpKV(1, 1);
    }

    CP_WAIT1();
    __syncthreads();

    uint32_t aq[4][4];
    #pragma unroll
    for (int kc = 0; kc < 4; kc++) {
        uint32_t addr = smb + FQOFF
                      + (uint32_t)((wid * 16 + (lane & 15)) * FPITCH
                                   + (kc * 16 + ((lane >> 4) << 3)) * 2);
        ldsm_x4(aq[kc], addr);
    }

    float oacc[8][4];
    #pragma unroll
    for (int n = 0; n < 8; n++)
        #pragma unroll
        for (int e = 0; e < 4; e++) oacc[n][e] = 0.f;
    float l0 = 0.f, l1 = 0.f;

    for (int it = 0; it < NIT; it++) {
        if (it > 0) {
            if (it + 1 < NIT) { CP_WAIT1(); } else { CP_WAIT0(); }
            __syncthreads();
        }
        const int st = it & 1;
        const uint32_t ks = smb + FKOFF + st * FSTG;
        const uint32_t vs = ks + 64 * FPITCH;
        const int* Mi = (const int*)(fsm + FMOFF + st * 256);

        float sacc[8][4];
        #pragma unroll
        for (int j = 0; j < 8; j++)
            #pragma unroll
            for (int e = 0; e < 4; e++) sacc[j][e] = 0.f;

        #pragma unroll
        for (int kc = 0; kc < 4; kc++) {
            uint32_t bfr[4][4];
            #pragma unroll
            for (int jj = 0; jj < 4; jj++) {
                uint32_t addr = ks + (uint32_t)((jj * 16 + ((lane >> 4) << 3) + (lane & 7)) * FPITCH
                                                + (kc * 16 + (((lane >> 3) & 1) << 3)) * 2);
                ldsm_x4(bfr[jj], addr);
            }
            #pragma unroll
            for (int jj = 0; jj < 4; jj++) {
                uint32_t b0[2] = { bfr[jj][0], bfr[jj][1] };
                uint32_t b1[2] = { bfr[jj][2], bfr[jj][3] };
                mma_bf16(sacc[2 * jj],     aq[kc], b0);
                mma_bf16(sacc[2 * jj + 1], aq[kc], b1);
            }
        }

        uint32_t pf[8][2];
        #pragma unroll
        for (int j = 0; j < 8; j++) {
            const int col = j * 8 + t4 * 2;
            const int m0 = Mi[col], m1 = Mi[col + 1];
            float s0 = m0 ? sacc[j][0] * 0.125f : 1e-9f;
            float s1 = m1 ? sacc[j][1] * 0.125f : 1e-9f;
            float s2 = m0 ? sacc[j][2] * 0.125f : 1e-9f;
            float s3 = m1 ? sacc[j][3] * 0.125f : 1e-9f;
            float p0 = __expf(s0), p1 = __expf(s1), p2 = __expf(s2), p3 = __expf(s3);
            l0 += p0 + p1;
            l1 += p2 + p3;
            pf[j][0] = cvt_bf2(p0, p1);
            pf[j][1] = cvt_bf2(p2, p3);
        }

        #pragma unroll
        for (int jk = 0; jk < 4; jk++) {
            uint32_t a[4] = { pf[2 * jk][0], pf[2 * jk][1], pf[2 * jk + 1][0], pf[2 * jk + 1][1] };
            #pragma unroll
            for (int nn = 0; nn < 4; nn++) {
                uint32_t bv[4];
                uint32_t addr = vs + (uint32_t)((jk * 16 + (((lane >> 3) & 1) << 3) + (lane & 7)) * FPITCH
                                                + (nn * 16 + ((lane >> 4) << 3)) * 2);
                ldsm_x4_t(bv, addr);
                uint32_t b0[2] = { bv[0], bv[1] };
                uint32_t b1[2] = { bv[2], bv[3] };
                mma_bf16(oacc[2 * nn],     a, b0);
                mma_bf16(oacc[2 * nn + 1], a, b1);
            }
        }

        __syncthreads();
        if (it + 2 < NIT) cpKV(it + 2, st);
    }

    l0 += __shfl_xor_sync(0xffffffffu, l0, 1);
    l0 += __shfl_xor_sync(0xffffffffu, l0, 2);
    l1 += __shfl_xor_sync(0xffffffffu, l1, 1);
    l1 += __shfl_xor_sync(0xffffffffu, l1, 2);
    const float inv0 = 1.f / l0, inv1 = 1.f / l1;

    const int r0 = b * SS + q0 + wid * 16 + gq;
    const int r1 = r0 + 8;
    #pragma unroll
    for (int nn = 0; nn < 8; nn++) {
        const int col = h * 64 + nn * 8 + t4 * 2;
        *(uint32_t*)(Ohi + (size_t)r0 * DD + col) =
            cvt_bf2(oacc[nn][0] * inv0, oacc[nn][1] * inv0);
        *(uint32_t*)(Ohi + (size_t)r1 * DD + col) =
            cvt_bf2(oacc[nn][2] * inv1, oacc[nn][3] * inv1);
    }
}

// ---------------------------------------------------------------- launch
extern "C" void kernel_launch(void* const* d_in, const int* in_sizes, int n_in,
                              void* d_out, int out_size)
{
    const float* x    = (const float*)d_in[0];
    const int*   mask = (const int*)  d_in[1];
    const float* wq   = (const float*)d_in[2];
    const float* wk   = (const float*)d_in[3];
    const float* wv   = (const float*)d_in[4];
    const float* wo   = (const float*)d_in[5];
    const float* w1   = (const float*)d_in[6];
    const float* b1   = (const float*)d_in[7];
    const float* w2   = (const float*)d_in[8];
    const float* b2   = (const float*)d_in[9];
    const float* ln1a = (const float*)d_in[10];
    const float* ln1b = (const float*)d_in[11];
    const float* ln2a = (const float*)d_in[12];
    const float* ln2b = (const float*)d_in[13];
    float* out = (float*)d_out;

    __nv_bfloat16 *thi, *chi, *qb, *kb, *vb;
    __nv_bfloat16 *wqhi, *wkhi, *wvhi, *wohi;
    __half *t16, *h1, *w1h, *w2h;
    float *x2;
    cudaGetSymbolAddress((void**)&thi, g_thi);
    cudaGetSymbolAddress((void**)&t16, g_t16);
    cudaGetSymbolAddress((void**)&chi, g_chi);
    cudaGetSymbolAddress((void**)&h1, g_h1);
    cudaGetSymbolAddress((void**)&qb, g_qb);     cudaGetSymbolAddress((void**)&kb, g_kb);
    cudaGetSymbolAddress((void**)&vb, g_vb);
    cudaGetSymbolAddress((void**)&wqhi, g_wqhi);
    cudaGetSymbolAddress((void**)&wkhi, g_wkhi);
    cudaGetSymbolAddress((void**)&wvhi, g_wvhi);
    cudaGetSymbolAddress((void**)&wohi, g_wohi);
    cudaGetSymbolAddress((void**)&w1h, g_w1h);
    cudaGetSymbolAddress((void**)&w2h, g_w2h);
    cudaGetSymbolAddress((void**)&x2, g_x2);

    cudaFuncSetAttribute(mma_gemm<0>, cudaFuncAttributeMaxDynamicSharedMemorySize, GSMEM);
    cudaFuncSetAttribute(mma_gemm<1>, cudaFuncAttributeMaxDynamicSharedMemorySize, GSMEM);
    cudaFuncSetAttribute(flash_mma, cudaFuncAttributeMaxDynamicSharedMemorySize, FSMEM);

    // merged prologue: weight transpose + LN1 (+x2 = x seed)
    WSArgs wa = {};
    wa.W[0] = wq; wa.Hi[0] = wqhi; wa.dt[0] = 0; wa.Kd[0] = DD; wa.Nd[0] = DD;
    wa.W[1] = wk; wa.Hi[1] = wkhi; wa.dt[1] = 0; wa.Kd[1] = DD; wa.Nd[1] = DD;
    wa.W[2] = wv; wa.Hi[2] = wvhi; wa.dt[2] = 0; wa.Kd[2] = DD; wa.Nd[2] = DD;
    wa.W[3] = wo; wa.Hi[3] = wohi; wa.dt[3] = 0; wa.Kd[3] = DD; wa.Nd[3] = DD;
    wa.W[4] = w1; wa.Hi[4] = w1h;  wa.dt[4] = 1; wa.Kd[4] = DD; wa.Nd[4] = FF;
    wa.W[5] = w2; wa.Hi[5] = w2h;  wa.dt[5] = 1; wa.Kd[5] = FF; wa.Nd[5] = DD;
    int acc0 = 0;
    wa.start[0] = 0;
    for (int e = 0; e < 6; e++) {
        acc0 += (wa.Nd[e] / 32) * (wa.Kd[e] / 32);
        wa.start[e + 1] = acc0;
    }
    prolog_kernel<<<acc0 + NROW, 256>>>(wa, x, thi, ln1a, ln1b, x2);

    // Q/K/V projections (bf16, z-batched)
    GemmArgs aq = {};
    aq.A = thi;
    aq.B0 = wqhi; aq.B1 = wkhi; aq.B2 = wvhi;
    aq.S0 = qb; aq.S1 = kb; aq.S2 = vb;
    aq.N = DD; aq.K = DD; aq.splitk = 1;
    mma_gemm<0><<<dim3(DD / 128, NROW / 128, 3), 256, GSMEM>>>(aq);

    // attention -> bf16 context (128 queries / CTA)
    flash_mma<<<dim3(BB * HH, SS / 128), 256, FSMEM>>>(qb, kb, vb, mask, chi);

    // x2 += ctx @ wo (bf16, split-K=3, vector red; x2 pre-seeded with x)
    GemmArgs ao = {};
    ao.A = chi;
    ao.B0 = wohi;
    ao.C0 = x2;
    ao.N = DD; ao.K = DD; ao.splitk = 3;
    mma_gemm<0><<<dim3(DD / 128, NROW / 128, 3), 256, GSMEM>>>(ao);

    // LN2 -> fp16 (seeds out = x2 + b2 for the FFN2 split-K reds)
    ln_kernel<1><<<NROW, 256>>>(x2, t16, ln2a, ln2b, out, b2);

    // FFN1: h1 = relu(t @ w1 + b1) (fp16)
    GemmArgs a1 = {};
    a1.A = t16;
    a1.B0 = w1h;
    a1.bias = b1; a1.relu = 1;
    a1.S0 = h1;
    a1.N = FF; a1.K = DD; a1.splitk = 1;
    mma_gemm<1><<<dim3(FF / 128, NROW / 128, 1), 256, GSMEM>>>(a1);

    // FFN2: out += h1 @ w2 (fp16, split-K=3, vector red; out pre-seeded with x2 + b2)
    GemmArgs a2 = {};
    a2.A = h1;
    a2.B0 = w2h;
    a2.C0 = out;
    a2.N = DD; a2.K = FF; a2.splitk = 3;
    mma_gemm<1><<<dim3(DD / 128, NROW / 128, 3), 256, GSMEM>>>(a2);
}

// round 16
// speedup vs baseline: 1.2842x; 1.0101x over previous
#include <cuda_runtime.h>
#include <cuda_bf16.h>
#include <cuda_fp16.h>
#include <cstdint>
#include <math.h>

#define BB 2
#define SS 2048
#define DD 768
#define FF 3072
#define HH 12
#define DKK 64
#define NROW (BB*SS)   // 4096

// ---------------------------------------------------------------- scratch
__device__ __nv_bfloat16 g_thi[NROW*DD];
__device__ __half        g_t16[NROW*DD];
__device__ __nv_bfloat16 g_qb[NROW*DD], g_kb[NROW*DD], g_vb[NROW*DD];
__device__ float g_x2[NROW*DD];
__device__ __nv_bfloat16 g_chi[NROW*DD];
__device__ __half        g_h1[NROW*FF];
__device__ __nv_bfloat16 g_wqhi[DD*DD];
__device__ __nv_bfloat16 g_wkhi[DD*DD];
__device__ __nv_bfloat16 g_wvhi[DD*DD];
__device__ __nv_bfloat16 g_wohi[DD*DD];
__device__ __half        g_w1h[FF*DD];   // [F,D] = w1^T (fp16)
__device__ __half        g_w2h[DD*FF];   // [D,F] = w2^T (fp16)

// ---------------------------------------------------------------- helpers
__device__ __forceinline__ uint32_t smem_to_u32(const void* p) {
    uint32_t a;
    asm("{ .reg .u64 t; cvta.to.shared.u64 t, %1; cvt.u32.u64 %0, t; }" : "=r"(a) : "l"(p));
    return a;
}
__device__ __forceinline__ void ldsm_x4(uint32_t (&r)[4], uint32_t addr) {
    asm volatile("ldmatrix.sync.aligned.m8n8.x4.shared.b16 {%0,%1,%2,%3}, [%4];"
                 : "=r"(r[0]), "=r"(r[1]), "=r"(r[2]), "=r"(r[3]) : "r"(addr));
}
__device__ __forceinline__ void ldsm_x4_t(uint32_t (&r)[4], uint32_t addr) {
    asm volatile("ldmatrix.sync.aligned.m8n8.x4.trans.shared.b16 {%0,%1,%2,%3}, [%4];"
                 : "=r"(r[0]), "=r"(r[1]), "=r"(r[2]), "=r"(r[3]) : "r"(addr));
}
__device__ __forceinline__ void mma_bf16(float (&c)[4], const uint32_t (&a)[4], const uint32_t (&b)[2]) {
    asm volatile("mma.sync.aligned.m16n8k16.row.col.f32.bf16.bf16.f32 "
                 "{%0,%1,%2,%3}, {%4,%5,%6,%7}, {%8,%9}, {%0,%1,%2,%3};"
                 : "+f"(c[0]), "+f"(c[1]), "+f"(c[2]), "+f"(c[3])
                 : "r"(a[0]), "r"(a[1]), "r"(a[2]), "r"(a[3]), "r"(b[0]), "r"(b[1]));
}
__device__ __forceinline__ void mma_f16(float (&c)[4], const uint32_t (&a)[4], const uint32_t (&b)[2]) {
    asm volatile("mma.sync.aligned.m16n8k16.row.col.f32.f16.f16.f32 "
                 "{%0,%1,%2,%3}, {%4,%5,%6,%7}, {%8,%9}, {%0,%1,%2,%3};"
                 : "+f"(c[0]), "+f"(c[1]), "+f"(c[2]), "+f"(c[3])
                 : "r"(a[0]), "r"(a[1]), "r"(a[2]), "r"(a[3]), "r"(b[0]), "r"(b[1]));
}
__device__ __forceinline__ void cp16(uint32_t dst, const void* src) {
    asm volatile("cp.async.cg.shared.global [%0], [%1], 16;" :: "r"(dst), "l"(src));
}
#define CP_COMMIT() asm volatile("cp.async.commit_group;" ::: "memory")
#define CP_WAIT1()  asm volatile("cp.async.wait_group 1;" ::: "memory")
#define CP_WAIT0()  asm volatile("cp.async.wait_group 0;" ::: "memory")

__device__ __forceinline__ uint32_t cvt_bf2(float lo, float hi) {
    uint32_t r;
    asm("cvt.rn.bf16x2.f32 %0, %1, %2;" : "=r"(r) : "f"(hi), "f"(lo));
    return r;
}
__device__ __forceinline__ void red_add2(float* addr, float vx, float vy) {
    asm volatile("red.global.add.v2.f32 [%0], {%1, %2};"
                 :: "l"(addr), "f"(vx), "f"(vy) : "memory");
}

template<int DT> struct Elem    { using T = __nv_bfloat16; };
template<>       struct Elem<1> { using T = __half; };

template<int DT>
__device__ __forceinline__ void mma_t(float (&c)[4], const uint32_t (&a)[4], const uint32_t (&b)[2]) {
    if constexpr (DT == 0) mma_bf16(c, a, b); else mma_f16(c, a, b);
}
template<int DT>
__device__ __forceinline__ uint32_t pack_t(float x, float y) {
    if constexpr (DT == 0) {
        return cvt_bf2(x, y);
    } else {
        __half2 h = __floats2half2_rn(x, y);
        return *(uint32_t*)&h;
    }
}

// ---------------------------------------------------------------- LayerNorm -> T
// zbuf (optional): initialized to x + zbias (residual/bias pre-seed for split-K reds)
template<int DT>
__global__ void ln_kernel(const float* __restrict__ x,
                          typename Elem<DT>::T* __restrict__ hi,
                          const float* __restrict__ alpha_p, const float* __restrict__ bias_p,
                          float* __restrict__ zbuf, const float* __restrict__ zbias)
{
    const int row = blockIdx.x;
    const float* xr = x + (size_t)row * DD;
    const int tid = threadIdx.x, lane = tid & 31, wid = tid >> 5;
    __shared__ float red[8], red2[8];
    __shared__ float s_mean, s_scale;

    float v0 = xr[tid], v1 = xr[tid + 256], v2 = xr[tid + 512];

    if (zbuf) {
        float* zr = zbuf + (size_t)row * DD;
        zr[tid]       = v0 + (zbias ? zbias[tid]       : 0.f);
        zr[tid + 256] = v1 + (zbias ? zbias[tid + 256] : 0.f);
        zr[tid + 512] = v2 + (zbias ? zbias[tid + 512] : 0.f);
    }

    float s  = v0 + v1 + v2;
    float s2 = v0 * v0 + v1 * v1 + v2 * v2;
    #pragma unroll
    for (int o = 16; o; o >>= 1) {
        s  += __shfl_xor_sync(0xffffffffu, s, o);
        s2 += __shfl_xor_sync(0xffffffffu, s2, o);
    }
    if (lane == 0) { red[wid] = s; red2[wid] = s2; }
    __syncthreads();
    if (tid == 0) {
        float t = 0.f, t2 = 0.f;
        #pragma unroll
        for (int i = 0; i < 8; i++) { t += red[i]; t2 += red2[i]; }
        const float mean = t / (float)DD;
        const float var = (t2 - (float)DD * mean * mean) / (float)(DD - 1);
        s_mean = mean;
        s_scale = alpha_p[0] / (sqrtf(fmaxf(var, 0.f)) + 1e-6f);
    }
    __syncthreads();
    const float mean = s_mean, scale = s_scale, bias = bias_p[0];

    float y0 = (v0 - mean) * scale + bias;
    float y1 = (v1 - mean) * scale + bias;
    float y2 = (v2 - mean) * scale + bias;
    if constexpr (DT == 0) {
        hi[(size_t)row * DD + tid]       = __float2bfloat16(y0);
        hi[(size_t)row * DD + tid + 256] = __float2bfloat16(y1);
        hi[(size_t)row * DD + tid + 512] = __float2bfloat16(y2);
    } else {
        hi[(size_t)row * DD + tid]       = __float2half(y0);
        hi[(size_t)row * DD + tid + 256] = __float2half(y1);
        hi[(size_t)row * DD + tid + 512] = __float2half(y2);
    }
}

// ---------------------------------------------------------------- merged prologue: weight transpose (64x64 vectorized) + LN1
struct WSArgs {
    const float* W[6];
    void* Hi[6];
    int dt[6];
    int Kd[6], Nd[6];
    int start[7];   // start[6] = total ws blocks (64x64 tiles)
};

__global__ void prolog_kernel(WSArgs a,
                              const float* __restrict__ x,
                              __nv_bfloat16* __restrict__ thi,
                              const float* __restrict__ alpha_p, const float* __restrict__ bias_p,
                              float* __restrict__ zbuf)
{
    __shared__ float ts[64][65];
    __shared__ float red[8], red2[8];
    __shared__ float s_mean, s_scale;

    const int tid = threadIdx.x;
    int bidx = blockIdx.x;

    if (bidx < a.start[6]) {
        // ---- weight transpose/convert branch (64x64 tile, vectorized)
        int e = 0;
        while (bidx >= a.start[e + 1]) e++;
        const int rel = bidx - a.start[e];
        const int Kd = a.Kd[e], Nd = a.Nd[e];
        const int nx = Nd / 64;
        const int n0 = (rel % nx) * 64, k0 = (rel / nx) * 64;
        const float* W = a.W[e];
        void* Hi = a.Hi[e];
        const int dt = a.dt[e];

        // load: 64 rows x 64 cols fp32; thread (r = tid>>2, c4 = tid&3), 4 float4 each
        const int r = tid >> 2, c4 = tid & 3;
        const float* wr = W + (size_t)(k0 + r) * Nd + n0;
        #pragma unroll
        for (int j = 0; j < 4; j++) {
            const int col = (j * 4 + c4) * 4;          // lanes cover contiguous 64B
            float4 v = *(const float4*)(wr + col);
            ts[r][col + 0] = v.x;
            ts[r][col + 1] = v.y;
            ts[r][col + 2] = v.z;
            ts[r][col + 3] = v.w;
        }
        __syncthreads();

        // store: thread (nn = tid>>2, kq = tid&3) owns 16 consecutive k of row nn
        const int nn = tid >> 2, kq = tid & 3;
        const size_t rowo = (size_t)(n0 + nn) * Kd + k0 + kq * 16;
        #pragma unroll
        for (int hh = 0; hh < 2; hh++) {
            float f[8];
            #pragma unroll
            for (int i = 0; i < 8; i++) f[i] = ts[kq * 16 + hh * 8 + i][nn];
            uint4 w;
            if (dt == 0) {
                w.x = cvt_bf2(f[0], f[1]); w.y = cvt_bf2(f[2], f[3]);
                w.z = cvt_bf2(f[4], f[5]); w.w = cvt_bf2(f[6], f[7]);
                *(uint4*)((__nv_bfloat16*)Hi + rowo + hh * 8) = w;
            } else {
                __half2 h0 = __floats2half2_rn(f[0], f[1]);
                __half2 h1 = __floats2half2_rn(f[2], f[3]);
                __half2 h2 = __floats2half2_rn(f[4], f[5]);
                __half2 h3 = __floats2half2_rn(f[6], f[7]);
                w.x = *(uint32_t*)&h0; w.y = *(uint32_t*)&h1;
                w.z = *(uint32_t*)&h2; w.w = *(uint32_t*)&h3;
                *(uint4*)((__half*)Hi + rowo + hh * 8) = w;
            }
        }
        return;
    }

    // ---- LN1 branch; seed x2 row with x (residual pre-add for WO split-K)
    const int row = bidx - a.start[6];
    const float* xr = x + (size_t)row * DD;
    const int lane = tid & 31, wid = tid >> 5;

    float v0 = xr[tid], v1 = xr[tid + 256], v2 = xr[tid + 512];
    {
        float* zr = zbuf + (size_t)row * DD;
        zr[tid]       = v0;
        zr[tid + 256] = v1;
        zr[tid + 512] = v2;
    }

    float s  = v0 + v1 + v2;
    float s2 = v0 * v0 + v1 * v1 + v2 * v2;
    #pragma unroll
    for (int o = 16; o; o >>= 1) {
        s  += __shfl_xor_sync(0xffffffffu, s, o);
        s2 += __shfl_xor_sync(0xffffffffu, s2, o);
    }
    if (lane == 0) { red[wid] = s; red2[wid] = s2; }
    __syncthreads();
    if (tid == 0) {
        float tt = 0.f, t2 = 0.f;
        #pragma unroll
        for (int i = 0; i < 8; i++) { tt += red[i]; t2 += red2[i]; }
        const float mean = tt / (float)DD;
        const float var = (t2 - (float)DD * mean * mean) / (float)(DD - 1);
        s_mean = mean;
        s_scale = alpha_p[0] / (sqrtf(fmaxf(var, 0.f)) + 1e-6f);
    }
    __syncthreads();
    const float mean = s_mean, scale = s_scale, bias = bias_p[0];

    thi[(size_t)row * DD + tid]       = __float2bfloat16((v0 - mean) * scale + bias);
    thi[(size_t)row * DD + tid + 256] = __float2bfloat16((v1 - mean) * scale + bias);
    thi[(size_t)row * DD + tid + 512] = __float2bfloat16((v2 - mean) * scale + bias);
}

// ---------------------------------------------------------------- HMMA GEMM: 8 warps, warp tile 64x32, 2-stage K64
// C = A @ B^T, B given [N,K]; DT: 0=bf16, 1=fp16. 16 warps/SM via 2 CTAs.
// splitk > 1: blockIdx.z indexes a K-partition; partials red.v2 into
// pre-seeded C (residual/bias already folded in by the producer kernel).
struct GemmArgs {
    const void *A;
    const void *B0, *B1, *B2;
    float *C0, *C1, *C2;
    const float *bias, *res;
    void *S0, *S1, *S2;          // optional T outputs (not valid with splitk)
    int relu, N, K, splitk;
};

#define GP 144                        // row pitch bytes for 64-elem (128B) rows
#define GTILE (128 * GP)              // 18432
#define GSTG  (2 * GTILE)             // 36864 (A + B)
#define GSMEM (2 * GSTG)              // 73728 (2 stages)

template<int DT>
__global__ void __launch_bounds__(256, 2) mma_gemm(GemmArgs ga)
{
    using T = typename Elem<DT>::T;
    extern __shared__ char smc[];
    const uint32_t smb = smem_to_u32(smc);
    const int tid = threadIdx.x, wid = tid >> 5, lane = tid & 31;
    const int bn = blockIdx.x * 128, bm = blockIdx.y * 128;
    const int z = blockIdx.z;
    const int sk = ga.splitk;
    const T* A = (const T*)ga.A;
    const T* B; float* C; T* Sh;
    int c0, NC;
    if (sk > 1) {
        B = (const T*)ga.B0; C = ga.C0; Sh = nullptr;
        NC = ga.K / 64 / sk;
        c0 = z * NC;
    } else {
        B = (const T*)((z == 0) ? ga.B0 : ((z == 1) ? ga.B1 : ga.B2));
        C = (z == 0) ? ga.C0 : ((z == 1) ? ga.C1 : ga.C2);
        Sh = (T*)((z == 0) ? ga.S0 : ((z == 1) ? ga.S1 : ga.S2));
        NC = ga.K / 64;
        c0 = 0;
    }
    const int K = ga.K;

    const int wm64 = (wid & 1) * 64;       // 2 warps over M
    const int wn32 = (wid >> 1) * 32;      // 4 warps over N

    float acc[4][4][4];
    #pragma unroll
    for (int f = 0; f < 4; f++)
        #pragma unroll
        for (int n = 0; n < 4; n++)
            #pragma unroll
            for (int e = 0; e < 4; e++) acc[f][n][e] = 0.f;

    auto issue = [&](int c) {
        const int ks = (c0 + c) * 64;
        const uint32_t base = smb + (uint32_t)(c & 1) * GSTG;
        #pragma unroll
        for (int i = 0; i < 8; i++) {
            const int u = tid + i * 256;                 // 0..2047
            const int row = (u >> 3) & 127, c16 = u & 7;
            const uint32_t dst = base + ((u < 1024) ? 0u : (uint32_t)GTILE)
                               + row * GP + c16 * 16;
            const T* src = (u < 1024)
                ? (A + (size_t)(bm + row) * K + ks + c16 * 8)
                : (B + (size_t)(bn + row) * K + ks + c16 * 8);
            cp16(dst, src);
        }
        CP_COMMIT();
    };

    issue(0);
    if (NC > 1) issue(1);

    const uint32_t aBase0 = smb + (uint32_t)((wm64 + (lane & 15)) * GP + ((lane >> 4) << 3) * 2);
    const uint32_t bBase0 = smb + (uint32_t)GTILE
                          + (uint32_t)((wn32 + ((lane >> 4) << 3) + (lane & 7)) * GP
                                       + (((lane >> 3) & 1) << 3) * 2);

    for (int c = 0; c < NC; c++) {
        if (c + 1 < NC) { CP_WAIT1(); } else { CP_WAIT0(); }
        __syncthreads();

        const uint32_t stg = (uint32_t)(c & 1) * GSTG;
        uint32_t aAddr = aBase0 + stg;
        uint32_t bAddr = bBase0 + stg;
        #pragma unroll
        for (int kk = 0; kk < 4; kk++) {
            uint32_t af[4][4];
            #pragma unroll
            for (int f = 0; f < 4; f++)
                ldsm_x4(af[f], aAddr + (uint32_t)(f * 16 * GP));
            uint32_t bq[2][4];
            #pragma unroll
            for (int p = 0; p < 2; p++)
                ldsm_x4(bq[p], bAddr + (uint32_t)(p * 16 * GP));
            aAddr += 32;
            bAddr += 32;
            #pragma unroll
            for (int f = 0; f < 4; f++) {
                #pragma unroll
                for (int p = 0; p < 2; p++) {
                    uint32_t b0[2] = { bq[p][0], bq[p][1] };
                    uint32_t b1[2] = { bq[p][2], bq[p][3] };
                    mma_t<DT>(acc[f][2 * p],     af[f], b0);
                    mma_t<DT>(acc[f][2 * p + 1], af[f], b1);
                }
            }
        }
        __syncthreads();                     // buffer (c&1) free for reuse
        if (c + 2 < NC) issue(c + 2);
    }

    // ---- epilogue
    const int gq = lane >> 2, t4 = lane & 3;
    #pragma unroll
    for (int f = 0; f < 4; f++) {
        #pragma unroll
        for (int half = 0; half < 2; half++) {
            const int m = bm + wm64 + f * 16 + gq + half * 8;
            const size_t rowo = (size_t)m * ga.N;
            #pragma unroll
            for (int n = 0; n < 4; n++) {
                const int col = bn + wn32 + n * 8 + t4 * 2;
                float vx = acc[f][n][half * 2 + 0];
                float vy = acc[f][n][half * 2 + 1];
                if (sk > 1) {
                    red_add2(C + rowo + col, vx, vy);      // C pre-seeded with res(+bias)
                    continue;
                }
                if (ga.bias) {
                    float2 bb = *(const float2*)(ga.bias + col);
                    vx += bb.x; vy += bb.y;
                }
                if (ga.relu) { vx = fmaxf(vx, 0.f); vy = fmaxf(vy, 0.f); }
                if (ga.res) {
                    float2 rr = *(const float2*)(ga.res + rowo + col);
                    vx += rr.x; vy += rr.y;
                }
                if (Sh) {
                    *(uint32_t*)(Sh + rowo + col) = pack_t<DT>(vx, vy);
                } else {
                    *(float2*)(C + rowo + col) = make_float2(vx, vy);
                }
            }
        }
    }
}

// ---------------------------------------------------------------- HMMA flash attention (bf16) — R10 config
#define FPITCH 144
#define FQOFF 0
#define FQSZ  (128 * FPITCH)                 // 18432
#define FKOFF FQSZ
#define FSTG  (2 * 64 * FPITCH)              // 18432 (K + V per stage)
#define FMOFF (FKOFF + 2 * FSTG)             // 55296
#define FSMEM (FMOFF + 512)                  // 55808

__global__ void __launch_bounds__(256, 2) flash_mma(
    const __nv_bfloat16* __restrict__ Qb, const __nv_bfloat16* __restrict__ Kb,
    const __nv_bfloat16* __restrict__ Vb, const int* __restrict__ mask,
    __nv_bfloat16* __restrict__ Ohi)
{
    extern __shared__ char fsm[];
    const uint32_t smb = smem_to_u32(fsm);
    const int tid = threadIdx.x, wid = tid >> 5, lane = tid & 31;
    const int gq = lane >> 2, t4 = lane & 3;
    const int bh = blockIdx.x, b = bh / HH, h = bh % HH;
    const int q0 = blockIdx.y * 128;
    const int NIT = SS / 64;

    auto cpKV = [&](int it, int st) {
        const uint32_t ks = smb + FKOFF + st * FSTG;
        const uint32_t vs = ks + 64 * FPITCH;
        const __nv_bfloat16* Ksrc = Kb + (size_t)(b * SS + it * 64) * DD + h * 64;
        const __nv_bfloat16* Vsrc = Vb + (size_t)(b * SS + it * 64) * DD + h * 64;
        #pragma unroll
        for (int i = 0; i < 2; i++) {
            const int idx = tid + i * 256;                 // 0..511
            const int r = idx >> 3, c = idx & 7;
            cp16(ks + r * FPITCH + c * 16, Ksrc + (size_t)r * DD + c * 8);
            cp16(vs + r * FPITCH + c * 16, Vsrc + (size_t)r * DD + c * 8);
        }
        if (tid < 16)
            cp16(smb + FMOFF + st * 256 + tid * 16, mask + b * SS + it * 64 + tid * 4);
        CP_COMMIT();
    };

    {
        const __nv_bfloat16* Qsrc = Qb + (size_t)(b * SS + q0) * DD + h * 64;
        #pragma unroll
        for (int i = 0; i < 4; i++) {
            const int idx = tid + i * 256;                 // 0..1023
            const int r = idx >> 3, c = idx & 7;
            cp16(smb + FQOFF + r * FPITCH + c * 16, Qsrc + (size_t)r * DD + c * 8);
        }
        const uint32_t ks = smb + FKOFF;
        const uint32_t vs = ks + 64 * FPITCH;
        const __nv_bfloat16* Ksrc = Kb + (size_t)(b * SS) * DD + h * 64;
        const __nv_bfloat16* Vsrc = Vb + (size_t)(b * SS) * DD + h * 64;
        #pragma unroll
        for (int i = 0; i < 2; i++) {
            const int idx = tid + i * 256;
            const int r = idx >> 3, c = idx & 7;
            cp16(ks + r * FPITCH + c * 16, Ksrc + (size_t)r * DD + c * 8);
            cp16(vs + r * FPITCH + c * 16, Vsrc + (size_t)r * DD + c * 8);
        }
        if (tid < 16)
            cp16(smb + FMOFF + tid * 16, mask + b * SS + tid * 4);
        CP_COMMIT();
        cpKV(1, 1);
    }

    CP_WAIT1();
    __syncthreads();

    uint32_t aq[4][4];
    #pragma unroll
    for (int kc = 0; kc < 4; kc++) {
        uint32_t addr = smb + FQOFF
                      + (uint32_t)((wid * 16 + (lane & 15)) * FPITCH
                                   + (kc * 16 + ((lane >> 4) << 3)) * 2);
        ldsm_x4(aq[kc], addr);
    }

    float oacc[8][4];
    #pragma unroll
    for (int n = 0; n < 8; n++)
        #pragma unroll
        for (int e = 0; e < 4; e++) oacc[n][e] = 0.f;
    float l0 = 0.f, l1 = 0.f;

    for (int it = 0; it < NIT; it++) {
        if (it > 0) {
            if (it + 1 < NIT) { CP_WAIT1(); } else { CP_WAIT0(); }
            __syncthreads();
        }
        const int st = it & 1;
        const uint32_t ks = smb + FKOFF + st * FSTG;
        const uint32_t vs = ks + 64 * FPITCH;
        const int* Mi = (const int*)(fsm + FMOFF + st * 256);

        float sacc[8][4];
        #pragma unroll
        for (int j = 0; j < 8; j++)
            #pragma unroll
            for (int e = 0; e < 4; e++) sacc[j][e] = 0.f;

        #pragma unroll
        for (int kc = 0; kc < 4; kc++) {
            uint32_t bfr[4][4];
            #pragma unroll
            for (int jj = 0; jj < 4; jj++) {
                uint32_t addr = ks + (uint32_t)((jj * 16 + ((lane >> 4) << 3) + (lane & 7)) * FPITCH
                                                + (kc * 16 + (((lane >> 3) & 1) << 3)) * 2);
                ldsm_x4(bfr[jj], addr);
            }
            #pragma unroll
            for (int jj = 0; jj < 4; jj++) {
                uint32_t b0[2] = { bfr[jj][0], bfr[jj][1] };
                uint32_t b1[2] = { bfr[jj][2], bfr[jj][3] };
                mma_bf16(sacc[2 * jj],     aq[kc], b0);
                mma_bf16(sacc[2 * jj + 1], aq[kc], b1);
            }
        }

        uint32_t pf[8][2];
        #pragma unroll
        for (int j = 0; j < 8; j++) {
            const int col = j * 8 + t4 * 2;
            const int m0 = Mi[col], m1 = Mi[col + 1];
            float s0 = m0 ? sacc[j][0] * 0.125f : 1e-9f;
            float s1 = m1 ? sacc[j][1] * 0.125f : 1e-9f;
            float s2 = m0 ? sacc[j][2] * 0.125f : 1e-9f;
            float s3 = m1 ? sacc[j][3] * 0.125f : 1e-9f;
            float p0 = __expf(s0), p1 = __expf(s1), p2 = __expf(s2), p3 = __expf(s3);
            l0 += p0 + p1;
            l1 += p2 + p3;
            pf[j][0] = cvt_bf2(p0, p1);
            pf[j][1] = cvt_bf2(p2, p3);
        }

        #pragma unroll
        for (int jk = 0; jk < 4; jk++) {
            uint32_t a[4] = { pf[2 * jk][0], pf[2 * jk][1], pf[2 * jk + 1][0], pf[2 * jk + 1][1] };
            #pragma unroll
            for (int nn = 0; nn < 4; nn++) {
                uint32_t bv[4];
                uint32_t addr = vs + (uint32_t)((jk * 16 + (((lane >> 3) & 1) << 3) + (lane & 7)) * FPITCH
                                                + (nn * 16 + ((lane >> 4) << 3)) * 2);
                ldsm_x4_t(bv, addr);
                uint32_t b0[2] = { bv[0], bv[1] };
                uint32_t b1[2] = { bv[2], bv[3] };
                mma_bf16(oacc[2 * nn],     a, b0);
                mma_bf16(oacc[2 * nn + 1], a, b1);
            }
        }

        __syncthreads();
        if (it + 2 < NIT) cpKV(it + 2, st);
    }

    l0 += __shfl_xor_sync(0xffffffffu, l0, 1);
    l0 += __shfl_xor_sync(0xffffffffu, l0, 2);
    l1 += __shfl_xor_sync(0xffffffffu, l1, 1);
    l1 += __shfl_xor_sync(0xffffffffu, l1, 2);
    const float inv0 = 1.f / l0, inv1 = 1.f / l1;

    const int r0 = b * SS + q0 + wid * 16 + gq;
    const int r1 = r0 + 8;
    #pragma unroll
    for (int nn = 0; nn < 8; nn++) {
        const int col = h * 64 + nn * 8 + t4 * 2;
        *(uint32_t*)(Ohi + (size_t)r0 * DD + col) =
            cvt_bf2(oacc[nn][0] * inv0, oacc[nn][1] * inv0);
        *(uint32_t*)(Ohi + (size_t)r1 * DD + col) =
            cvt_bf2(oacc[nn][2] * inv1, oacc[nn][3] * inv1);
    }
}

// ---------------------------------------------------------------- launch
extern "C" void kernel_launch(void* const* d_in, const int* in_sizes, int n_in,
                              void* d_out, int out_size)
{
    const float* x    = (const float*)d_in[0];
    const int*   mask = (const int*)  d_in[1];
    const float* wq   = (const float*)d_in[2];
    const float* wk   = (const float*)d_in[3];
    const float* wv   = (const float*)d_in[4];
    const float* wo   = (const float*)d_in[5];
    const float* w1   = (const float*)d_in[6];
    const float* b1   = (const float*)d_in[7];
    const float* w2   = (const float*)d_in[8];
    const float* b2   = (const float*)d_in[9];
    const float* ln1a = (const float*)d_in[10];
    const float* ln1b = (const float*)d_in[11];
    const float* ln2a = (const float*)d_in[12];
    const float* ln2b = (const float*)d_in[13];
    float* out = (float*)d_out;

    __nv_bfloat16 *thi, *chi, *qb, *kb, *vb;
    __nv_bfloat16 *wqhi, *wkhi, *wvhi, *wohi;
    __half *t16, *h1, *w1h, *w2h;
    float *x2;
    cudaGetSymbolAddress((void**)&thi, g_thi);
    cudaGetSymbolAddress((void**)&t16, g_t16);
    cudaGetSymbolAddress((void**)&chi, g_chi);
    cudaGetSymbolAddress((void**)&h1, g_h1);
    cudaGetSymbolAddress((void**)&qb, g_qb);     cudaGetSymbolAddress((void**)&kb, g_kb);
    cudaGetSymbolAddress((void**)&vb, g_vb);
    cudaGetSymbolAddress((void**)&wqhi, g_wqhi);
    cudaGetSymbolAddress((void**)&wkhi, g_wkhi);
    cudaGetSymbolAddress((void**)&wvhi, g_wvhi);
    cudaGetSymbolAddress((void**)&wohi, g_wohi);
    cudaGetSymbolAddress((void**)&w1h, g_w1h);
    cudaGetSymbolAddress((void**)&w2h, g_w2h);
    cudaGetSymbolAddress((void**)&x2, g_x2);

    cudaFuncSetAttribute(mma_gemm<0>, cudaFuncAttributeMaxDynamicSharedMemorySize, GSMEM);
    cudaFuncSetAttribute(mma_gemm<1>, cudaFuncAttributeMaxDynamicSharedMemorySize, GSMEM);
    cudaFuncSetAttribute(flash_mma, cudaFuncAttributeMaxDynamicSharedMemorySize, FSMEM);

    // merged prologue: weight transpose (64x64 tiles) + LN1 (+x2 = x seed)
    WSArgs wa = {};
    wa.W[0] = wq; wa.Hi[0] = wqhi; wa.dt[0] = 0; wa.Kd[0] = DD; wa.Nd[0] = DD;
    wa.W[1] = wk; wa.Hi[1] = wkhi; wa.dt[1] = 0; wa.Kd[1] = DD; wa.Nd[1] = DD;
    wa.W[2] = wv; wa.Hi[2] = wvhi; wa.dt[2] = 0; wa.Kd[2] = DD; wa.Nd[2] = DD;
    wa.W[3] = wo; wa.Hi[3] = wohi; wa.dt[3] = 0; wa.Kd[3] = DD; wa.Nd[3] = DD;
    wa.W[4] = w1; wa.Hi[4] = w1h;  wa.dt[4] = 1; wa.Kd[4] = DD; wa.Nd[4] = FF;
    wa.W[5] = w2; wa.Hi[5] = w2h;  wa.dt[5] = 1; wa.Kd[5] = FF; wa.Nd[5] = DD;
    int acc0 = 0;
    wa.start[0] = 0;
    for (int e = 0; e < 6; e++) {
        acc0 += (wa.Nd[e] / 64) * (wa.Kd[e] / 64);
        wa.start[e + 1] = acc0;
    }
    prolog_kernel<<<acc0 + NROW, 256>>>(wa, x, thi, ln1a, ln1b, x2);

    // Q/K/V projections (bf16, z-batched)
    GemmArgs aq = {};
    aq.A = thi;
    aq.B0 = wqhi; aq.B1 = wkhi; aq.B2 = wvhi;
    aq.S0 = qb; aq.S1 = kb; aq.S2 = vb;
    aq.N = DD; aq.K = DD; aq.splitk = 1;
    mma_gemm<0><<<dim3(DD / 128, NROW / 128, 3), 256, GSMEM>>>(aq);

    // attention -> bf16 context (128 queries / CTA)
    flash_mma<<<dim3(BB * HH, SS / 128), 256, FSMEM>>>(qb, kb, vb, mask, chi);

    // x2 += ctx @ wo (bf16, split-K=3, vector red; x2 pre-seeded with x)
    GemmArgs ao = {};
    ao.A = chi;
    ao.B0 = wohi;
    ao.C0 = x2;
    ao.N = DD; ao.K = DD; ao.splitk = 3;
    mma_gemm<0><<<dim3(DD / 128, NROW / 128, 3), 256, GSMEM>>>(ao);

    // LN2 -> fp16 (seeds out = x2 + b2 for the FFN2 split-K reds)
    ln_kernel<1><<<NROW, 256>>>(x2, t16, ln2a, ln2b, out, b2);

    // FFN1: h1 = relu(t @ w1 + b1) (fp16)
    GemmArgs a1 = {};
    a1.A = t16;
    a1.B0 = w1h;
    a1.bias = b1; a1.relu = 1;
    a1.S0 = h1;
    a1.N = FF; a1.K = DD; a1.splitk = 1;
    mma_gemm<1><<<dim3(FF / 128, NROW / 128, 1), 256, GSMEM>>>(a1);

    // FFN2: out += h1 @ w2 (fp16, split-K=3, vector red; out pre-seeded with x2 + b2)
    GemmArgs a2 = {};
    a2.A = h1;
    a2.B0 = w2h;
    a2.C0 = out;
    a2.N = DD; a2.K = FF; a2.splitk = 3;
    mma_gemm<1><<<dim3(DD / 128, NROW / 128, 3), 256, GSMEM>>>(a2);
}